// round 1
// baseline (speedup 1.0000x reference)
#include <cuda_runtime.h>
#include <cuda_bf16.h>
#include <math.h>

#define BB 2
#define TT 2048
#define DD 1024
#define HH 16
#define HDIM 64
#define FF 4096
#define NROWS (BB*TT)          // 4096
#define NBH (BB*HH)            // 32

// ---------------- scratch (device globals; no allocation allowed) ----------------
__device__ float g_h[NROWS*DD];        // LN1 output
__device__ float g_q[NROWS*DD];
__device__ float g_k[NROWS*DD];
__device__ float g_v[NROWS*DD];
__device__ float g_att[NROWS*DD];
__device__ float g_x2[NROWS*DD];       // x + att@w_proj + b_proj
__device__ float g_h2[NROWS*DD];       // LN2 output
__device__ float g_ff[NROWS*FF];       // relu(h2@w1+b1)
__device__ float g_scores[(size_t)NBH*TT*TT];  // 512MB attention scores / probs

// ---------------- LayerNorm: one block per row ----------------
__global__ void ln_kernel(const float* __restrict__ x, const float* __restrict__ g,
                          const float* __restrict__ b, float* __restrict__ out) {
    int row = blockIdx.x;
    const float* xr = x + (size_t)row * DD;
    float* orow = out + (size_t)row * DD;
    __shared__ float sm[256];
    int tid = threadIdx.x;

    float s = 0.f;
    for (int i = tid; i < DD; i += 256) s += xr[i];
    sm[tid] = s; __syncthreads();
    for (int o = 128; o > 0; o >>= 1) { if (tid < o) sm[tid] += sm[tid+o]; __syncthreads(); }
    float mean = sm[0] * (1.0f / DD);
    __syncthreads();

    float v = 0.f;
    for (int i = tid; i < DD; i += 256) { float d = xr[i] - mean; v += d * d; }
    sm[tid] = v; __syncthreads();
    for (int o = 128; o > 0; o >>= 1) { if (tid < o) sm[tid] += sm[tid+o]; __syncthreads(); }
    float inv = rsqrtf(sm[0] * (1.0f / DD) + 1e-5f);

    for (int i = tid; i < DD; i += 256)
        orow[i] = (xr[i] - mean) * inv * g[i] + b[i];
}

// ---------------- RoPE (in-place on [B,T,D] with heads packed in D) ----------------
__global__ void rope_kernel(float* __restrict__ p) {
    int idx = blockIdx.x * blockDim.x + threadIdx.x;
    const int total = BB*TT*HH*(HDIM/2);
    if (idx >= total) return;
    int i = idx & 31;                 // pair index 0..31
    int h = (idx >> 5) & (HH-1);
    int t = (idx >> 9) & (TT-1);
    int b = idx >> 20;                // 9 + 11
    float theta = expf(-((2.0f * i) / (float)HDIM) * logf(10000.0f));
    float ang = (float)t * theta;
    float c = cosf(ang), sn = sinf(ang);
    float* q = p + ((size_t)(b*TT + t) * DD) + h*HDIM + 2*i;
    float x1 = q[0], x2 = q[1];
    q[0] = x1 * c - x2 * sn;
    q[1] = x1 * sn + x2 * c;
}

// ---------------- Generic tiled GEMM: C = A[M,K] @ B[K,N] (+bias)(+relu)(+res) ----------------
template<bool HASBIAS, bool RELU, bool HASRES>
__global__ void gemm_kernel(const float* __restrict__ A, const float* __restrict__ Bm,
                            const float* __restrict__ bias, const float* __restrict__ res,
                            float* __restrict__ C, int M, int N, int K) {
    __shared__ float As[64][17];   // [m][kk]
    __shared__ float Bs[16][64];   // [kk][n]
    int tid = threadIdx.x;
    int tx = tid & 15, ty = tid >> 4;
    int rowBase = blockIdx.y * 64;
    int colBase = blockIdx.x * 64;
    float acc[4][4];
#pragma unroll
    for (int i = 0; i < 4; i++)
#pragma unroll
        for (int j = 0; j < 4; j++) acc[i][j] = 0.f;

    for (int k0 = 0; k0 < K; k0 += 16) {
#pragma unroll
        for (int i = tid; i < 1024; i += 256) {
            int m = i >> 4, kk = i & 15;
            As[m][kk] = A[(size_t)(rowBase + m) * K + k0 + kk];
        }
#pragma unroll
        for (int i = tid; i < 1024; i += 256) {
            int kk = i >> 6, n = i & 63;
            Bs[kk][n] = Bm[(size_t)(k0 + kk) * N + colBase + n];
        }
        __syncthreads();
#pragma unroll
        for (int kk = 0; kk < 16; kk++) {
            float a[4], bv[4];
#pragma unroll
            for (int i = 0; i < 4; i++) a[i] = As[ty*4 + i][kk];
#pragma unroll
            for (int j = 0; j < 4; j++) bv[j] = Bs[kk][tx*4 + j];
#pragma unroll
            for (int i = 0; i < 4; i++)
#pragma unroll
                for (int j = 0; j < 4; j++) acc[i][j] += a[i] * bv[j];
        }
        __syncthreads();
    }

#pragma unroll
    for (int i = 0; i < 4; i++) {
        int row = rowBase + ty*4 + i;
#pragma unroll
        for (int j = 0; j < 4; j++) {
            int col = colBase + tx*4 + j;
            float v = acc[i][j];
            if (HASBIAS) v += bias[col];
            if (RELU)    v = fmaxf(v, 0.f);
            if (HASRES)  v += res[(size_t)row * N + col];
            C[(size_t)row * N + col] = v;
        }
    }
}

// ---------------- Scores: S[b,h,t,s] = scale * q.k + mask ----------------
__global__ void scores_kernel(const float* __restrict__ q, const float* __restrict__ k,
                              const int* __restrict__ mask, float* __restrict__ S) {
    __shared__ float Qs[64][65];
    __shared__ float Ks[64][65];
    int bh = blockIdx.z;
    int b = bh >> 4, h = bh & 15;
    int t0 = blockIdx.y * 64;
    int s0 = blockIdx.x * 64;
    int tid = threadIdx.x;
    int tx = tid & 15, ty = tid >> 4;

    for (int i = tid; i < 4096; i += 256) {
        int r = i >> 6, d = i & 63;
        Qs[r][d] = q[((size_t)(b*TT) + t0 + r) * DD + h*HDIM + d];
        Ks[r][d] = k[((size_t)(b*TT) + s0 + r) * DD + h*HDIM + d];
    }
    __syncthreads();

    float acc[4][4];
#pragma unroll
    for (int i = 0; i < 4; i++)
#pragma unroll
        for (int j = 0; j < 4; j++) acc[i][j] = 0.f;

#pragma unroll 8
    for (int kk = 0; kk < 64; kk++) {
        float a[4], bv[4];
#pragma unroll
        for (int i = 0; i < 4; i++) a[i] = Qs[ty*4 + i][kk];
#pragma unroll
        for (int j = 0; j < 4; j++) bv[j] = Ks[tx*4 + j][kk];
#pragma unroll
        for (int i = 0; i < 4; i++)
#pragma unroll
            for (int j = 0; j < 4; j++) acc[i][j] += a[i] * bv[j];
    }

    const float scale = 0.125f;  // 1/sqrt(64)
#pragma unroll
    for (int i = 0; i < 4; i++) {
        int t = t0 + ty*4 + i;
#pragma unroll
        for (int j = 0; j < 4; j++) {
            int s = s0 + tx*4 + j;
            float v = acc[i][j] * scale;
            int mv = mask[((size_t)b * TT + t) * TT + s];
            if (mv == 0) v = -1e30f;
            S[((size_t)bh * TT + t) * TT + s] = v;
        }
    }
}

// ---------------- Softmax over last dim (T=2048), one block per row ----------------
__global__ void softmax_kernel(float* __restrict__ S) {
    size_t row = blockIdx.x;
    float* r = S + row * TT;
    int tid = threadIdx.x;
    __shared__ float sm[256];

    float vals[8];
#pragma unroll
    for (int u = 0; u < 8; u++) vals[u] = r[tid + u*256];

    float m = -1e30f;
#pragma unroll
    for (int u = 0; u < 8; u++) m = fmaxf(m, vals[u]);
    sm[tid] = m; __syncthreads();
    for (int o = 128; o > 0; o >>= 1) { if (tid < o) sm[tid] = fmaxf(sm[tid], sm[tid+o]); __syncthreads(); }
    m = sm[0]; __syncthreads();

    float s = 0.f;
#pragma unroll
    for (int u = 0; u < 8; u++) { vals[u] = expf(vals[u] - m); s += vals[u]; }
    sm[tid] = s; __syncthreads();
    for (int o = 128; o > 0; o >>= 1) { if (tid < o) sm[tid] += sm[tid+o]; __syncthreads(); }
    float inv = 1.0f / sm[0];

#pragma unroll
    for (int u = 0; u < 8; u++) r[tid + u*256] = vals[u] * inv;
}

// ---------------- AV: att[b,t,h*64+d] = sum_s P[bh,t,s] * v[b,s,h*64+d] ----------------
__global__ void av_kernel(const float* __restrict__ P, const float* __restrict__ v,
                          float* __restrict__ att) {
    __shared__ float Ps[64][17];
    __shared__ float Vs[16][64];
    int bh = blockIdx.y;
    int b = bh >> 4, h = bh & 15;
    int t0 = blockIdx.x * 64;
    int tid = threadIdx.x;
    int tx = tid & 15, ty = tid >> 4;

    float acc[4][4];
#pragma unroll
    for (int i = 0; i < 4; i++)
#pragma unroll
        for (int j = 0; j < 4; j++) acc[i][j] = 0.f;

    for (int k0 = 0; k0 < TT; k0 += 16) {
        for (int i = tid; i < 1024; i += 256) {
            int m = i >> 4, kk = i & 15;
            Ps[m][kk] = P[((size_t)bh * TT + t0 + m) * TT + k0 + kk];
        }
        for (int i = tid; i < 1024; i += 256) {
            int kk = i >> 6, n = i & 63;
            Vs[kk][n] = v[((size_t)(b*TT) + k0 + kk) * DD + h*HDIM + n];
        }
        __syncthreads();
#pragma unroll
        for (int kk = 0; kk < 16; kk++) {
            float a[4], bv[4];
#pragma unroll
            for (int i = 0; i < 4; i++) a[i] = Ps[ty*4 + i][kk];
#pragma unroll
            for (int j = 0; j < 4; j++) bv[j] = Vs[kk][tx*4 + j];
#pragma unroll
            for (int i = 0; i < 4; i++)
#pragma unroll
                for (int j = 0; j < 4; j++) acc[i][j] += a[i] * bv[j];
        }
        __syncthreads();
    }

#pragma unroll
    for (int i = 0; i < 4; i++) {
        int t = t0 + ty*4 + i;
#pragma unroll
        for (int j = 0; j < 4; j++) {
            int d = tx*4 + j;
            att[((size_t)(b*TT) + t) * DD + h*HDIM + d] = acc[i][j];
        }
    }
}

// ---------------- launch ----------------
static float* symaddr(const void* sym) {
    void* p = nullptr;
    cudaGetSymbolAddress(&p, sym);
    return (float*)p;
}

extern "C" void kernel_launch(void* const* d_in, const int* in_sizes, int n_in,
                              void* d_out, int out_size) {
    const float* x      = (const float*)d_in[0];
    const int*   mask   = (const int*)  d_in[1];
    const float* wq     = (const float*)d_in[2];
    const float* wk     = (const float*)d_in[3];
    const float* wv     = (const float*)d_in[4];
    const float* w_proj = (const float*)d_in[5];
    const float* b_proj = (const float*)d_in[6];
    const float* ln1_g  = (const float*)d_in[7];
    const float* ln1_b  = (const float*)d_in[8];
    const float* ln2_g  = (const float*)d_in[9];
    const float* ln2_b  = (const float*)d_in[10];
    const float* w1     = (const float*)d_in[11];
    const float* b1     = (const float*)d_in[12];
    const float* w2     = (const float*)d_in[13];
    const float* b2     = (const float*)d_in[14];
    float* out = (float*)d_out;

    float* h_   = symaddr(g_h);
    float* q_   = symaddr(g_q);
    float* k_   = symaddr(g_k);
    float* v_   = symaddr(g_v);
    float* att_ = symaddr(g_att);
    float* x2_  = symaddr(g_x2);
    float* h2_  = symaddr(g_h2);
    float* ff_  = symaddr(g_ff);
    float* sc_  = symaddr(g_scores);

    // 1) LN1
    ln_kernel<<<NROWS, 256>>>(x, ln1_g, ln1_b, h_);

    // 2) Q,K,V projections (M=4096, N=1024, K=1024)
    dim3 gQKV(DD/64, NROWS/64);
    gemm_kernel<false,false,false><<<gQKV, 256>>>(h_, wq, nullptr, nullptr, q_, NROWS, DD, DD);
    gemm_kernel<false,false,false><<<gQKV, 256>>>(h_, wk, nullptr, nullptr, k_, NROWS, DD, DD);
    gemm_kernel<false,false,false><<<gQKV, 256>>>(h_, wv, nullptr, nullptr, v_, NROWS, DD, DD);

    // 3) RoPE on q,k
    {
        int total = BB*TT*HH*(HDIM/2);
        int blocks = (total + 255) / 256;
        rope_kernel<<<blocks, 256>>>(q_);
        rope_kernel<<<blocks, 256>>>(k_);
    }

    // 4) scores + mask
    {
        dim3 g(TT/64, TT/64, NBH);
        scores_kernel<<<g, 256>>>(q_, k_, mask, sc_);
    }

    // 5) softmax
    softmax_kernel<<<NBH*TT, 256>>>(sc_);

    // 6) att = P @ V
    {
        dim3 g(TT/64, NBH);
        av_kernel<<<g, 256>>>(sc_, v_, att_);
    }

    // 7) x2 = x + att@w_proj + b_proj
    gemm_kernel<true,false,true><<<dim3(DD/64, NROWS/64), 256>>>(att_, w_proj, b_proj, x, x2_, NROWS, DD, DD);

    // 8) LN2
    ln_kernel<<<NROWS, 256>>>(x2_, ln2_g, ln2_b, h2_);

    // 9) ff = relu(h2@w1 + b1)   (M=4096, N=4096, K=1024)
    gemm_kernel<true,true,false><<<dim3(FF/64, NROWS/64), 256>>>(h2_, w1, b1, nullptr, ff_, NROWS, FF, DD);

    // 10) out = x2 + ff@w2 + b2  (M=4096, N=1024, K=4096)
    gemm_kernel<true,false,true><<<dim3(DD/64, NROWS/64), 256>>>(ff_, w2, b2, x2_, out, NROWS, DD, FF);
}

// round 2
// speedup vs baseline: 1.0005x; 1.0005x over previous
#include <cuda_runtime.h>
#include <cuda_bf16.h>
#include <math.h>

#define BB 2
#define TT 2048
#define DD 1024
#define HH 16
#define HDIM 64
#define FF 4096
#define NROWS (BB*TT)          // 4096
#define NBH (BB*HH)            // 32

// ---------------- scratch (device globals; no allocation allowed) ----------------
__device__ float g_h[NROWS*DD];        // LN1 output
__device__ float g_q[NROWS*DD];
__device__ float g_k[NROWS*DD];
__device__ float g_v[NROWS*DD];
__device__ float g_att[NROWS*DD];
__device__ float g_x2[NROWS*DD];       // x + att@w_proj + b_proj
__device__ float g_h2[NROWS*DD];       // LN2 output
__device__ float g_ff[NROWS*FF];       // relu(h2@w1+b1)
__device__ float g_scores[(size_t)NBH*TT*TT];  // 512MB attention scores / probs

// ---------------- LayerNorm: one block per row ----------------
__global__ void ln_kernel(const float* __restrict__ x, const float* __restrict__ g,
                          const float* __restrict__ b, float* __restrict__ out) {
    int row = blockIdx.x;
    const float* xr = x + (size_t)row * DD;
    float* orow = out + (size_t)row * DD;
    __shared__ float sm[256];
    int tid = threadIdx.x;

    float s = 0.f;
    for (int i = tid; i < DD; i += 256) s += xr[i];
    sm[tid] = s; __syncthreads();
    for (int o = 128; o > 0; o >>= 1) { if (tid < o) sm[tid] += sm[tid+o]; __syncthreads(); }
    float mean = sm[0] * (1.0f / DD);
    __syncthreads();

    float v = 0.f;
    for (int i = tid; i < DD; i += 256) { float d = xr[i] - mean; v += d * d; }
    sm[tid] = v; __syncthreads();
    for (int o = 128; o > 0; o >>= 1) { if (tid < o) sm[tid] += sm[tid+o]; __syncthreads(); }
    float inv = rsqrtf(sm[0] * (1.0f / DD) + 1e-5f);

    for (int i = tid; i < DD; i += 256)
        orow[i] = (xr[i] - mean) * inv * g[i] + b[i];
}

// ---------------- RoPE (in-place on [B,T,D] with heads packed in D) ----------------
__global__ void rope_kernel(float* __restrict__ p) {
    int idx = blockIdx.x * blockDim.x + threadIdx.x;
    const int total = BB*TT*HH*(HDIM/2);
    if (idx >= total) return;
    int i = idx & 31;                 // pair index 0..31
    int h = (idx >> 5) & (HH-1);
    int t = (idx >> 9) & (TT-1);
    int b = idx >> 20;                // 9 + 11
    float theta = expf(-((2.0f * i) / (float)HDIM) * logf(10000.0f));
    float ang = (float)t * theta;
    float c = cosf(ang), sn = sinf(ang);
    float* q = p + ((size_t)(b*TT + t) * DD) + h*HDIM + 2*i;
    float x1 = q[0], x2 = q[1];
    q[0] = x1 * c - x2 * sn;
    q[1] = x1 * sn + x2 * c;
}

// ---------------- Generic tiled GEMM: C = A[M,K] @ B[K,N] (+bias)(+relu)(+res) ----------------
template<bool HASBIAS, bool RELU, bool HASRES>
__global__ void gemm_kernel(const float* __restrict__ A, const float* __restrict__ Bm,
                            const float* __restrict__ bias, const float* __restrict__ res,
                            float* __restrict__ C, int M, int N, int K) {
    __shared__ float As[64][17];   // [m][kk]
    __shared__ float Bs[16][64];   // [kk][n]
    int tid = threadIdx.x;
    int tx = tid & 15, ty = tid >> 4;
    int rowBase = blockIdx.y * 64;
    int colBase = blockIdx.x * 64;
    float acc[4][4];
#pragma unroll
    for (int i = 0; i < 4; i++)
#pragma unroll
        for (int j = 0; j < 4; j++) acc[i][j] = 0.f;

    for (int k0 = 0; k0 < K; k0 += 16) {
#pragma unroll
        for (int i = tid; i < 1024; i += 256) {
            int m = i >> 4, kk = i & 15;
            As[m][kk] = A[(size_t)(rowBase + m) * K + k0 + kk];
        }
#pragma unroll
        for (int i = tid; i < 1024; i += 256) {
            int kk = i >> 6, n = i & 63;
            Bs[kk][n] = Bm[(size_t)(k0 + kk) * N + colBase + n];
        }
        __syncthreads();
#pragma unroll
        for (int kk = 0; kk < 16; kk++) {
            float a[4], bv[4];
#pragma unroll
            for (int i = 0; i < 4; i++) a[i] = As[ty*4 + i][kk];
#pragma unroll
            for (int j = 0; j < 4; j++) bv[j] = Bs[kk][tx*4 + j];
#pragma unroll
            for (int i = 0; i < 4; i++)
#pragma unroll
                for (int j = 0; j < 4; j++) acc[i][j] += a[i] * bv[j];
        }
        __syncthreads();
    }

#pragma unroll
    for (int i = 0; i < 4; i++) {
        int row = rowBase + ty*4 + i;
#pragma unroll
        for (int j = 0; j < 4; j++) {
            int col = colBase + tx*4 + j;
            float v = acc[i][j];
            if (HASBIAS) v += bias[col];
            if (RELU)    v = fmaxf(v, 0.f);
            if (HASRES)  v += res[(size_t)row * N + col];
            C[(size_t)row * N + col] = v;
        }
    }
}

// ---------------- Scores: S[b,h,t,s] = scale * q.k + mask ----------------
__global__ void scores_kernel(const float* __restrict__ q, const float* __restrict__ k,
                              const int* __restrict__ mask, float* __restrict__ S) {
    __shared__ float Qs[64][65];
    __shared__ float Ks[64][65];
    int bh = blockIdx.z;
    int b = bh >> 4, h = bh & 15;
    int t0 = blockIdx.y * 64;
    int s0 = blockIdx.x * 64;
    int tid = threadIdx.x;
    int tx = tid & 15, ty = tid >> 4;

    for (int i = tid; i < 4096; i += 256) {
        int r = i >> 6, d = i & 63;
        Qs[r][d] = q[((size_t)(b*TT) + t0 + r) * DD + h*HDIM + d];
        Ks[r][d] = k[((size_t)(b*TT) + s0 + r) * DD + h*HDIM + d];
    }
    __syncthreads();

    float acc[4][4];
#pragma unroll
    for (int i = 0; i < 4; i++)
#pragma unroll
        for (int j = 0; j < 4; j++) acc[i][j] = 0.f;

#pragma unroll 8
    for (int kk = 0; kk < 64; kk++) {
        float a[4], bv[4];
#pragma unroll
        for (int i = 0; i < 4; i++) a[i] = Qs[ty*4 + i][kk];
#pragma unroll
        for (int j = 0; j < 4; j++) bv[j] = Ks[tx*4 + j][kk];
#pragma unroll
        for (int i = 0; i < 4; i++)
#pragma unroll
            for (int j = 0; j < 4; j++) acc[i][j] += a[i] * bv[j];
    }

    const float scale = 0.125f;  // 1/sqrt(64)
#pragma unroll
    for (int i = 0; i < 4; i++) {
        int t = t0 + ty*4 + i;
#pragma unroll
        for (int j = 0; j < 4; j++) {
            int s = s0 + tx*4 + j;
            float v = acc[i][j] * scale;
            int mv = mask[((size_t)b * TT + t) * TT + s];
            if (mv == 0) v = -1e30f;
            S[((size_t)bh * TT + t) * TT + s] = v;
        }
    }
}

// ---------------- Softmax over last dim (T=2048), one block per row ----------------
__global__ void softmax_kernel(float* __restrict__ S) {
    size_t row = blockIdx.x;
    float* r = S + row * TT;
    int tid = threadIdx.x;
    __shared__ float sm[256];

    float vals[8];
#pragma unroll
    for (int u = 0; u < 8; u++) vals[u] = r[tid + u*256];

    float m = -1e30f;
#pragma unroll
    for (int u = 0; u < 8; u++) m = fmaxf(m, vals[u]);
    sm[tid] = m; __syncthreads();
    for (int o = 128; o > 0; o >>= 1) { if (tid < o) sm[tid] = fmaxf(sm[tid], sm[tid+o]); __syncthreads(); }
    m = sm[0]; __syncthreads();

    float s = 0.f;
#pragma unroll
    for (int u = 0; u < 8; u++) { vals[u] = expf(vals[u] - m); s += vals[u]; }
    sm[tid] = s; __syncthreads();
    for (int o = 128; o > 0; o >>= 1) { if (tid < o) sm[tid] += sm[tid+o]; __syncthreads(); }
    float inv = 1.0f / sm[0];

#pragma unroll
    for (int u = 0; u < 8; u++) r[tid + u*256] = vals[u] * inv;
}

// ---------------- AV: att[b,t,h*64+d] = sum_s P[bh,t,s] * v[b,s,h*64+d] ----------------
__global__ void av_kernel(const float* __restrict__ P, const float* __restrict__ v,
                          float* __restrict__ att) {
    __shared__ float Ps[64][17];
    __shared__ float Vs[16][64];
    int bh = blockIdx.y;
    int b = bh >> 4, h = bh & 15;
    int t0 = blockIdx.x * 64;
    int tid = threadIdx.x;
    int tx = tid & 15, ty = tid >> 4;

    float acc[4][4];
#pragma unroll
    for (int i = 0; i < 4; i++)
#pragma unroll
        for (int j = 0; j < 4; j++) acc[i][j] = 0.f;

    for (int k0 = 0; k0 < TT; k0 += 16) {
        for (int i = tid; i < 1024; i += 256) {
            int m = i >> 4, kk = i & 15;
            Ps[m][kk] = P[((size_t)bh * TT + t0 + m) * TT + k0 + kk];
        }
        for (int i = tid; i < 1024; i += 256) {
            int kk = i >> 6, n = i & 63;
            Vs[kk][n] = v[((size_t)(b*TT) + k0 + kk) * DD + h*HDIM + n];
        }
        __syncthreads();
#pragma unroll
        for (int kk = 0; kk < 16; kk++) {
            float a[4], bv[4];
#pragma unroll
            for (int i = 0; i < 4; i++) a[i] = Ps[ty*4 + i][kk];
#pragma unroll
            for (int j = 0; j < 4; j++) bv[j] = Vs[kk][tx*4 + j];
#pragma unroll
            for (int i = 0; i < 4; i++)
#pragma unroll
                for (int j = 0; j < 4; j++) acc[i][j] += a[i] * bv[j];
        }
        __syncthreads();
    }

#pragma unroll
    for (int i = 0; i < 4; i++) {
        int t = t0 + ty*4 + i;
#pragma unroll
        for (int j = 0; j < 4; j++) {
            int d = tx*4 + j;
            att[((size_t)(b*TT) + t) * DD + h*HDIM + d] = acc[i][j];
        }
    }
}

// ---------------- launch ----------------
static float* symaddr(const void* sym) {
    void* p = nullptr;
    cudaGetSymbolAddress(&p, sym);
    return (float*)p;
}

extern "C" void kernel_launch(void* const* d_in, const int* in_sizes, int n_in,
                              void* d_out, int out_size) {
    const float* x      = (const float*)d_in[0];
    const int*   mask   = (const int*)  d_in[1];
    const float* wq     = (const float*)d_in[2];
    const float* wk     = (const float*)d_in[3];
    const float* wv     = (const float*)d_in[4];
    const float* w_proj = (const float*)d_in[5];
    const float* b_proj = (const float*)d_in[6];
    const float* ln1_g  = (const float*)d_in[7];
    const float* ln1_b  = (const float*)d_in[8];
    const float* ln2_g  = (const float*)d_in[9];
    const float* ln2_b  = (const float*)d_in[10];
    const float* w1     = (const float*)d_in[11];
    const float* b1     = (const float*)d_in[12];
    const float* w2     = (const float*)d_in[13];
    const float* b2     = (const float*)d_in[14];
    float* out = (float*)d_out;

    float* h_   = symaddr(g_h);
    float* q_   = symaddr(g_q);
    float* k_   = symaddr(g_k);
    float* v_   = symaddr(g_v);
    float* att_ = symaddr(g_att);
    float* x2_  = symaddr(g_x2);
    float* h2_  = symaddr(g_h2);
    float* ff_  = symaddr(g_ff);
    float* sc_  = symaddr(g_scores);

    // 1) LN1
    ln_kernel<<<NROWS, 256>>>(x, ln1_g, ln1_b, h_);

    // 2) Q,K,V projections (M=4096, N=1024, K=1024)
    dim3 gQKV(DD/64, NROWS/64);
    gemm_kernel<false,false,false><<<gQKV, 256>>>(h_, wq, nullptr, nullptr, q_, NROWS, DD, DD);
    gemm_kernel<false,false,false><<<gQKV, 256>>>(h_, wk, nullptr, nullptr, k_, NROWS, DD, DD);
    gemm_kernel<false,false,false><<<gQKV, 256>>>(h_, wv, nullptr, nullptr, v_, NROWS, DD, DD);

    // 3) RoPE on q,k
    {
        int total = BB*TT*HH*(HDIM/2);
        int blocks = (total + 255) / 256;
        rope_kernel<<<blocks, 256>>>(q_);
        rope_kernel<<<blocks, 256>>>(k_);
    }

    // 4) scores + mask
    {
        dim3 g(TT/64, TT/64, NBH);
        scores_kernel<<<g, 256>>>(q_, k_, mask, sc_);
    }

    // 5) softmax
    softmax_kernel<<<NBH*TT, 256>>>(sc_);

    // 6) att = P @ V
    {
        dim3 g(TT/64, NBH);
        av_kernel<<<g, 256>>>(sc_, v_, att_);
    }

    // 7) x2 = x + att@w_proj + b_proj
    gemm_kernel<true,false,true><<<dim3(DD/64, NROWS/64), 256>>>(att_, w_proj, b_proj, x, x2_, NROWS, DD, DD);

    // 8) LN2
    ln_kernel<<<NROWS, 256>>>(x2_, ln2_g, ln2_b, h2_);

    // 9) ff = relu(h2@w1 + b1)   (M=4096, N=4096, K=1024)
    gemm_kernel<true,true,false><<<dim3(FF/64, NROWS/64), 256>>>(h2_, w1, b1, nullptr, ff_, NROWS, FF, DD);

    // 10) out = x2 + ff@w2 + b2  (M=4096, N=1024, K=4096)
    gemm_kernel<true,false,true><<<dim3(DD/64, NROWS/64), 256>>>(ff_, w2, b2, x2_, out, NROWS, DD, FF);
}

// round 4
// speedup vs baseline: 4.3562x; 4.3538x over previous
#include <cuda_runtime.h>
#include <cuda_bf16.h>
#include <cuda_fp16.h>
#include <cstdint>
#include <math.h>

#define BB 2
#define TT 2048
#define DD 1024
#define HH 16
#define FF 4096
#define NROWS (BB*TT)
#define NBH (BB*HH)
#define K3D (3*DD)     // 3072
#define K3F (3*FF)     // 12288

// ================= scratch =================
__device__ __align__(256) __nv_bfloat16 g_hs [NROWS*K3D];
__device__ __align__(256) float         g_qkv[3*(size_t)NROWS*DD];
__device__ __align__(256) __nv_bfloat16 g_atts[NROWS*K3D];
__device__ __align__(256) float         g_x2 [NROWS*DD];
__device__ __align__(256) __nv_bfloat16 g_h2s[NROWS*K3D];
__device__ __align__(256) __nv_bfloat16 g_ffs[(size_t)NROWS*K3F];
__device__ __align__(256) __nv_bfloat16 g_wqkvT[3*(size_t)DD*K3D];
__device__ __align__(256) __nv_bfloat16 g_wpT[(size_t)DD*K3D];
__device__ __align__(256) __nv_bfloat16 g_w1T[(size_t)FF*K3D];
__device__ __align__(256) __nv_bfloat16 g_w2T[(size_t)DD*K3F];
__device__ __align__(256) uint32_t      g_mb [BB*TT*(TT/32)];

// ================= helpers =================
__device__ __forceinline__ uint32_t smem_u32(const void* p) {
    uint32_t a;
    asm("{ .reg .u64 t; cvta.to.shared.u64 t, %1; cvt.u32.u64 %0, t; }" : "=r"(a) : "l"(p));
    return a;
}
#define CPA(dst, src) \
    asm volatile("cp.async.cg.shared.global [%0], [%1], 16;" :: "r"(dst), "l"(src) : "memory")
#define CPCOMMIT asm volatile("cp.async.commit_group;" ::: "memory")
#define CPWAIT(n) asm volatile("cp.async.wait_group %0;" :: "n"(n) : "memory")

__device__ __forceinline__ void ldsm4(uint32_t& r0, uint32_t& r1, uint32_t& r2, uint32_t& r3, uint32_t a) {
    asm volatile("ldmatrix.sync.aligned.m8n8.x4.shared.b16 {%0,%1,%2,%3}, [%4];"
        : "=r"(r0), "=r"(r1), "=r"(r2), "=r"(r3) : "r"(a));
}
__device__ __forceinline__ void ldsm4t(uint32_t& r0, uint32_t& r1, uint32_t& r2, uint32_t& r3, uint32_t a) {
    asm volatile("ldmatrix.sync.aligned.m8n8.x4.trans.shared.b16 {%0,%1,%2,%3}, [%4];"
        : "=r"(r0), "=r"(r1), "=r"(r2), "=r"(r3) : "r"(a));
}
__device__ __forceinline__ void mma_bf16(float* c, const uint32_t* a, uint32_t b0, uint32_t b1) {
    asm volatile("mma.sync.aligned.m16n8k16.row.col.f32.bf16.bf16.f32 "
        "{%0,%1,%2,%3}, {%4,%5,%6,%7}, {%8,%9}, {%0,%1,%2,%3};"
        : "+f"(c[0]), "+f"(c[1]), "+f"(c[2]), "+f"(c[3])
        : "r"(a[0]), "r"(a[1]), "r"(a[2]), "r"(a[3]), "r"(b0), "r"(b1));
}
__device__ __forceinline__ void mma_f16(float* c, const uint32_t* a, uint32_t b0, uint32_t b1) {
    asm volatile("mma.sync.aligned.m16n8k16.row.col.f32.f16.f16.f32 "
        "{%0,%1,%2,%3}, {%4,%5,%6,%7}, {%8,%9}, {%0,%1,%2,%3};"
        : "+f"(c[0]), "+f"(c[1]), "+f"(c[2]), "+f"(c[3])
        : "r"(a[0]), "r"(a[1]), "r"(a[2]), "r"(a[3]), "r"(b0), "r"(b1));
}
__device__ __forceinline__ void split2(float v, __nv_bfloat16& hi, __nv_bfloat16& lo) {
    hi = __float2bfloat16(v);
    lo = __float2bfloat16(v - __bfloat162float(hi));
}

// ================= LayerNorm -> split bf16 [Ah|Al|Ah] =================
__global__ void ln_split_kernel(const float* __restrict__ x, const float* __restrict__ g,
                                const float* __restrict__ b, __nv_bfloat16* __restrict__ out) {
    int row = blockIdx.x;
    const float* xr = x + (size_t)row * DD;
    __shared__ float sm[256];
    int tid = threadIdx.x;

    float s = 0.f;
    for (int i = tid; i < DD; i += 256) s += xr[i];
    sm[tid] = s; __syncthreads();
    for (int o = 128; o > 0; o >>= 1) { if (tid < o) sm[tid] += sm[tid+o]; __syncthreads(); }
    float mean = sm[0] * (1.0f / DD);
    __syncthreads();
    float v = 0.f;
    for (int i = tid; i < DD; i += 256) { float d = xr[i] - mean; v += d * d; }
    sm[tid] = v; __syncthreads();
    for (int o = 128; o > 0; o >>= 1) { if (tid < o) sm[tid] += sm[tid+o]; __syncthreads(); }
    float inv = rsqrtf(sm[0] * (1.0f / DD) + 1e-5f);

    __nv_bfloat16* orow = out + (size_t)row * K3D;
    for (int i = tid; i < DD; i += 256) {
        float val = (xr[i] - mean) * inv * g[i] + b[i];
        __nv_bfloat16 hi, lo; split2(val, hi, lo);
        orow[i] = hi; orow[DD + i] = lo; orow[2*DD + i] = hi;
    }
}

// ================= weight transpose+split: W[K,N] -> [N][3K] bf16 [Wh|Wh|Wl] ====
__global__ void wsplit_kernel(const float* __restrict__ W, __nv_bfloat16* __restrict__ out,
                              int K, int N) {
    __shared__ float t[32][33];
    int k0 = blockIdx.y * 32, n0 = blockIdx.x * 32;
    int tx = threadIdx.x, ty = threadIdx.y;   // 32 x 8
#pragma unroll
    for (int r = 0; r < 4; r++)
        t[ty + 8*r][tx] = W[(size_t)(k0 + ty + 8*r) * N + n0 + tx];
    __syncthreads();
#pragma unroll
    for (int r = 0; r < 4; r++) {
        int n = n0 + ty + 8*r;
        int k = k0 + tx;
        float v = t[tx][ty + 8*r];
        __nv_bfloat16 hi, lo; split2(v, hi, lo);
        size_t base = (size_t)n * 3 * K;
        out[base + k] = hi;
        out[base + K + k] = hi;
        out[base + 2*K + k] = lo;
    }
}

// ================= RoPE (exact fp32, in-place) =================
__global__ void rope_kernel(float* __restrict__ p) {
    int idx = blockIdx.x * blockDim.x + threadIdx.x;
    const int total = BB*TT*HH*32;
    if (idx >= total) return;
    int i = idx & 31;
    int h = (idx >> 5) & (HH-1);
    int t = (idx >> 9) & (TT-1);
    int b = idx >> 20;
    float theta = expf(-((2.0f * i) / 64.0f) * logf(10000.0f));
    float ang = (float)t * theta;
    float c = cosf(ang), sn = sinf(ang);
    float* q = p + ((size_t)(b*TT + t) * DD) + h*64 + 2*i;
    float x1 = q[0], x2 = q[1];
    q[0] = x1 * c - x2 * sn;
    q[1] = x1 * sn + x2 * c;
}

// ================= pack mask to bits =================
__global__ void packmask_kernel(const int* __restrict__ mask, uint32_t* __restrict__ mb) {
    int idx = blockIdx.x * 256 + threadIdx.x;
    uint32_t w = __ballot_sync(0xffffffffu, mask[idx] != 0);
    if ((threadIdx.x & 31) == 0) mb[idx >> 5] = w;
}

// ================= mma.sync GEMM: C[M,N] = A[M,K3] . Bw[N,K3]^T =================
// EPI bits: 2=BIAS, 4=RELU, 8=RES, 16=SPLIT-out
template<int EPI>
__global__ void __launch_bounds__(256) mm_bf16(
        const __nv_bfloat16* __restrict__ A, const __nv_bfloat16* __restrict__ Bw0,
        const float* __restrict__ bias, const float* __restrict__ res,
        float* __restrict__ outF0, __nv_bfloat16* __restrict__ outS,
        int N, int K3, long zsB, long zsC) {
    extern __shared__ char smem_raw[];
    const uint32_t sbr = smem_u32(smem_raw);
    const uint32_t sb = (sbr + 1023) & ~1023u;

    const int tid = threadIdx.x, wid = tid >> 5, lane = tid & 31;
    const int wm = wid >> 1, wn = wid & 1;
    const int m0 = blockIdx.y << 7, n0 = blockIdx.x << 7;
    const int NC = K3 >> 6;

    const __nv_bfloat16* Bw = Bw0 + (size_t)blockIdx.z * zsB;
    float* outF = outF0 + (size_t)blockIdx.z * zsC;

    const __nv_bfloat16* Ag = A  + (size_t)m0 * K3;
    const __nv_bfloat16* Bg = Bw + (size_t)n0 * K3;

    // per-thread load mapping
    const int rq_r = tid >> 3, rq_q = tid & 7;
    const __nv_bfloat16* agp = Ag + (size_t)rq_r * K3 + (rq_q << 3);
    const __nv_bfloat16* bgp = Bg + (size_t)rq_r * K3 + (rq_q << 3);
    uint32_t so = (uint32_t)((rq_r << 7) + (rq_q << 4));
    so ^= (so >> 3) & 0x70;
    const size_t rowstep = (size_t)32 * K3;

    auto issue_load = [&](int c, int stg) {
        uint32_t sA = sb + stg * 32768;
#pragma unroll
        for (int v = 0; v < 4; v++) {
            CPA(sA + so + v*4096,         agp + (size_t)c*64 + v*rowstep);
            CPA(sA + 16384 + so + v*4096, bgp + (size_t)c*64 + v*rowstep);
        }
    };

    float acc[2][8][4];
#pragma unroll
    for (int mi = 0; mi < 2; mi++)
#pragma unroll
        for (int ni = 0; ni < 8; ni++)
#pragma unroll
            for (int v = 0; v < 4; v++) acc[mi][ni][v] = 0.f;

    // prologue
#pragma unroll
    for (int s = 0; s < 3; s++) { issue_load(s, s); CPCOMMIT; }

    for (int c = 0; c < NC; c++) {
        CPWAIT(2);
        __syncthreads();
        int stg = c % 3;
        uint32_t sA = sb + stg * 32768;
        uint32_t sB = sA + 16384;
#pragma unroll
        for (int kk = 0; kk < 4; kk++) {
            uint32_t a[2][4], b0[8], b1[8];
            const int kb = kk*32 + ((lane >> 4) << 4);
#pragma unroll
            for (int mi = 0; mi < 2; mi++) {
                int row = wm*32 + mi*16 + (lane & 15);
                uint32_t o = (uint32_t)(row*128 + kb); o ^= (o >> 3) & 0x70;
                ldsm4(a[mi][0], a[mi][1], a[mi][2], a[mi][3], sA + o);
            }
#pragma unroll
            for (int j = 0; j < 4; j++) {
                int row = wn*64 + j*16 + (lane & 15);
                uint32_t o = (uint32_t)(row*128 + kb); o ^= (o >> 3) & 0x70;
                ldsm4(b0[2*j], b0[2*j+1], b1[2*j], b1[2*j+1], sB + o);
            }
#pragma unroll
            for (int mi = 0; mi < 2; mi++)
#pragma unroll
                for (int ni = 0; ni < 8; ni++)
                    mma_bf16(acc[mi][ni], a[mi], b0[ni], b1[ni]);
        }
        __syncthreads();
        if (c + 3 < NC) issue_load(c + 3, stg);
        CPCOMMIT;
    }
    CPWAIT(0);

    // epilogue
    const int g = lane >> 2, tq = lane & 3;
#pragma unroll
    for (int mi = 0; mi < 2; mi++) {
#pragma unroll
        for (int ni = 0; ni < 8; ni++) {
#pragma unroll
            for (int rh = 0; rh < 2; rh++) {
                int row = m0 + wm*32 + mi*16 + g + rh*8;
                int col = n0 + wn*64 + ni*8 + 2*tq;
#pragma unroll
                for (int vv = 0; vv < 2; vv++) {
                    float v = acc[mi][ni][rh*2 + vv];
                    int cc = col + vv;
                    if (EPI & 2) v += bias[cc];
                    if (EPI & 4) v = fmaxf(v, 0.f);
                    if (EPI & 8) v += res[(size_t)row * N + cc];
                    if (EPI & 16) {
                        __nv_bfloat16 hi, lo; split2(v, hi, lo);
                        size_t base = (size_t)row * 3 * N;
                        outS[base + cc]       = hi;
                        outS[base + N + cc]   = lo;
                        outS[base + 2*N + cc] = hi;
                    } else {
                        outF[(size_t)row * N + cc] = v;
                    }
                }
            }
        }
    }
}

// ================= flash attention: fp16 mma, online softmax =================
__global__ void __launch_bounds__(128) flash_kernel(
        const float* __restrict__ qg, const float* __restrict__ kg, const float* __restrict__ vg,
        const uint32_t* __restrict__ mb, __nv_bfloat16* __restrict__ attS) {
    extern __shared__ char smem_raw[];
    const uint32_t sbr = smem_u32(smem_raw);
    const uint32_t sb = (sbr + 1023) & ~1023u;
    char* base = smem_raw + (int)(sb - sbr);

    const uint32_t sQ = sb, sK = sb + 8192, sV = sb + 16384, sP = sb + 24576;
    uint32_t* mw = (uint32_t*)(base + 32768);

    int bh = blockIdx.y, b = bh >> 4, h = bh & 15;
    int t0 = blockIdx.x << 6;
    int tid = threadIdx.x, wid = tid >> 5, lane = tid & 31;
    int g = lane >> 2, tq = lane & 3;

    // load Q tile (fp32 -> fp16, swizzled)
    {
        const float* src = qg + ((size_t)(b*TT) + t0) * DD + h*64;
#pragma unroll
        for (int v = 0; v < 8; v++) {
            int p = tid + (v << 7);
            int t = p >> 4, dq = p & 15;
            float4 f = *(const float4*)(src + (size_t)t*DD + dq*4);
            __half2 h0 = __floats2half2_rn(f.x, f.y);
            __half2 h1 = __floats2half2_rn(f.z, f.w);
            uint2 st; st.x = *(uint32_t*)&h0; st.y = *(uint32_t*)&h1;
            uint32_t o = (uint32_t)(t*128 + dq*8); o ^= (o >> 3) & 0x70;
            *(uint2*)(base + o) = st;
        }
    }

    float mrow[2] = {-1e30f, -1e30f};
    float lrow[2] = {0.f, 0.f};
    float o[8][4];
#pragma unroll
    for (int ni = 0; ni < 8; ni++)
#pragma unroll
        for (int v = 0; v < 4; v++) o[ni][v] = 0.f;

    for (int s0 = 0; s0 < TT; s0 += 64) {
        __syncthreads();
        {
            const float* ks = kg + ((size_t)(b*TT) + s0) * DD + h*64;
            const float* vs = vg + ((size_t)(b*TT) + s0) * DD + h*64;
#pragma unroll
            for (int v = 0; v < 8; v++) {
                int p = tid + (v << 7);
                int t = p >> 4, dq = p & 15;
                uint32_t oo = (uint32_t)(t*128 + dq*8); oo ^= (oo >> 3) & 0x70;
                float4 f = *(const float4*)(ks + (size_t)t*DD + dq*4);
                __half2 h0 = __floats2half2_rn(f.x, f.y);
                __half2 h1 = __floats2half2_rn(f.z, f.w);
                uint2 st; st.x = *(uint32_t*)&h0; st.y = *(uint32_t*)&h1;
                *(uint2*)(base + 8192 + oo) = st;
                f = *(const float4*)(vs + (size_t)t*DD + dq*4);
                h0 = __floats2half2_rn(f.x, f.y);
                h1 = __floats2half2_rn(f.z, f.w);
                st.x = *(uint32_t*)&h0; st.y = *(uint32_t*)&h1;
                *(uint2*)(base + 16384 + oo) = st;
            }
            int t = tid >> 1, w = tid & 1;
            mw[tid] = mb[((size_t)(b*TT) + t0 + t)*(TT/32) + (s0 >> 5) + w];
        }
        __syncthreads();

        // S = Q K^T
        float sa[8][4];
#pragma unroll
        for (int ni = 0; ni < 8; ni++)
#pragma unroll
            for (int v = 0; v < 4; v++) sa[ni][v] = 0.f;
#pragma unroll
        for (int kk = 0; kk < 4; kk++) {
            const int kb = kk*32 + ((lane >> 4) << 4);
            uint32_t a[4], b0[8], b1[8];
            {
                int row = wid*16 + (lane & 15);
                uint32_t oo = (uint32_t)(row*128 + kb); oo ^= (oo >> 3) & 0x70;
                ldsm4(a[0], a[1], a[2], a[3], sQ + oo);
            }
#pragma unroll
            for (int j = 0; j < 4; j++) {
                int row = j*16 + (lane & 15);
                uint32_t oo = (uint32_t)(row*128 + kb); oo ^= (oo >> 3) & 0x70;
                ldsm4(b0[2*j], b0[2*j+1], b1[2*j], b1[2*j+1], sK + oo);
            }
#pragma unroll
            for (int ni = 0; ni < 8; ni++) mma_f16(sa[ni], a, b0[ni], b1[ni]);
        }

        // mask + scale
        uint32_t w00 = mw[(wid*16 + g)*2 + 0],     w01 = mw[(wid*16 + g)*2 + 1];
        uint32_t w10 = mw[(wid*16 + g + 8)*2 + 0], w11 = mw[(wid*16 + g + 8)*2 + 1];
#pragma unroll
        for (int ni = 0; ni < 8; ni++) {
#pragma unroll
            for (int v = 0; v < 4; v++) {
                int sc = ni*8 + 2*tq + (v & 1);
                uint32_t wsel = (v < 2) ? ((sc < 32) ? w00 : w01)
                                        : ((sc < 32) ? w10 : w11);
                bool ok = (wsel >> (sc & 31)) & 1u;
                sa[ni][v] = ok ? sa[ni][v]*0.125f : -1e30f;
            }
        }

        // online softmax (rows: rh=0 -> g, rh=1 -> g+8)
#pragma unroll
        for (int rh = 0; rh < 2; rh++) {
            float mx = -1e30f;
#pragma unroll
            for (int ni = 0; ni < 8; ni++)
                mx = fmaxf(mx, fmaxf(sa[ni][rh*2], sa[ni][rh*2+1]));
            mx = fmaxf(mx, __shfl_xor_sync(0xffffffffu, mx, 1));
            mx = fmaxf(mx, __shfl_xor_sync(0xffffffffu, mx, 2));
            float mn = fmaxf(mrow[rh], mx);
            float alpha = __expf(mrow[rh] - mn);
            mrow[rh] = mn;
            float rs = 0.f;
#pragma unroll
            for (int ni = 0; ni < 8; ni++) {
                float p0 = __expf(sa[ni][rh*2]   - mn);
                float p1 = __expf(sa[ni][rh*2+1] - mn);
                sa[ni][rh*2] = p0; sa[ni][rh*2+1] = p1;
                rs += p0 + p1;
            }
            rs += __shfl_xor_sync(0xffffffffu, rs, 1);
            rs += __shfl_xor_sync(0xffffffffu, rs, 2);
            lrow[rh] = lrow[rh]*alpha + rs;
#pragma unroll
            for (int ni = 0; ni < 8; ni++) { o[ni][rh*2] *= alpha; o[ni][rh*2+1] *= alpha; }
        }

        // P -> smem fp16 (own rows only)
#pragma unroll
        for (int ni = 0; ni < 8; ni++) {
#pragma unroll
            for (int rh = 0; rh < 2; rh++) {
                int trow = wid*16 + g + rh*8;
                int scol = ni*8 + 2*tq;
                __half2 hp = __floats2half2_rn(sa[ni][rh*2], sa[ni][rh*2+1]);
                uint32_t oo = (uint32_t)(trow*128 + scol*2); oo ^= (oo >> 3) & 0x70;
                *(uint32_t*)(base + 24576 + oo) = *(uint32_t*)&hp;
            }
        }
        __syncwarp();

        // O += P V
#pragma unroll
        for (int kk = 0; kk < 4; kk++) {
            uint32_t a[4], b0[8], b1[8];
            {
                int row = wid*16 + (lane & 15);
                uint32_t oo = (uint32_t)(row*128 + kk*32 + ((lane >> 4) << 4));
                oo ^= (oo >> 3) & 0x70;
                ldsm4(a[0], a[1], a[2], a[3], sP + oo);
            }
#pragma unroll
            for (int j = 0; j < 4; j++) {
                int rs_ = kk*16 + (lane & 15);
                uint32_t oo = (uint32_t)(rs_*128 + j*32 + ((lane >> 4) << 4));
                oo ^= (oo >> 3) & 0x70;
                ldsm4t(b0[2*j], b1[2*j], b0[2*j+1], b1[2*j+1], sV + oo);
            }
#pragma unroll
            for (int ni = 0; ni < 8; ni++) mma_f16(o[ni], a, b0[ni], b1[ni]);
        }
    }

    // write att (split bf16 [hi|lo|hi])
#pragma unroll
    for (int rh = 0; rh < 2; rh++) {
        float inv = 1.0f / lrow[rh];
        int t = t0 + wid*16 + g + rh*8;
        size_t rb = ((size_t)(b*TT) + t) * K3D;
#pragma unroll
        for (int ni = 0; ni < 8; ni++) {
#pragma unroll
            for (int vv = 0; vv < 2; vv++) {
                int col = h*64 + ni*8 + 2*tq + vv;
                float val = o[ni][rh*2 + vv] * inv;
                __nv_bfloat16 hi, lo; split2(val, hi, lo);
                attS[rb + col]        = hi;
                attS[rb + DD + col]   = lo;
                attS[rb + 2*DD + col] = hi;
            }
        }
    }
}

// ================= launch =================
template<typename T>
static T* symaddr(const void* sym) {
    void* p = nullptr;
    cudaGetSymbolAddress(&p, sym);
    return (T*)p;
}

extern "C" void kernel_launch(void* const* d_in, const int* in_sizes, int n_in,
                              void* d_out, int out_size) {
    const float* x      = (const float*)d_in[0];
    const int*   mask   = (const int*)  d_in[1];
    const float* wq     = (const float*)d_in[2];
    const float* wk     = (const float*)d_in[3];
    const float* wv     = (const float*)d_in[4];
    const float* w_proj = (const float*)d_in[5];
    const float* b_proj = (const float*)d_in[6];
    const float* ln1_g  = (const float*)d_in[7];
    const float* ln1_b  = (const float*)d_in[8];
    const float* ln2_g  = (const float*)d_in[9];
    const float* ln2_b  = (const float*)d_in[10];
    const float* w1     = (const float*)d_in[11];
    const float* b1     = (const float*)d_in[12];
    const float* w2     = (const float*)d_in[13];
    const float* b2     = (const float*)d_in[14];
    float* out = (float*)d_out;

    __nv_bfloat16* hs   = symaddr<__nv_bfloat16>(g_hs);
    float*         qkv  = symaddr<float>(g_qkv);
    __nv_bfloat16* atts = symaddr<__nv_bfloat16>(g_atts);
    float*         x2_  = symaddr<float>(g_x2);
    __nv_bfloat16* h2s  = symaddr<__nv_bfloat16>(g_h2s);
    __nv_bfloat16* ffs  = symaddr<__nv_bfloat16>(g_ffs);
    __nv_bfloat16* wqkvT= symaddr<__nv_bfloat16>(g_wqkvT);
    __nv_bfloat16* wpT  = symaddr<__nv_bfloat16>(g_wpT);
    __nv_bfloat16* w1T  = symaddr<__nv_bfloat16>(g_w1T);
    __nv_bfloat16* w2T  = symaddr<__nv_bfloat16>(g_w2T);
    uint32_t*      mb   = symaddr<uint32_t>(g_mb);

    const int SMEM_MM = 3*32768 + 1024;   // 99328
    const int SMEM_FL = 33280 + 1024;     // 34304
    cudaFuncSetAttribute(mm_bf16<0>,  cudaFuncAttributeMaxDynamicSharedMemorySize, SMEM_MM);
    cudaFuncSetAttribute(mm_bf16<10>, cudaFuncAttributeMaxDynamicSharedMemorySize, SMEM_MM);
    cudaFuncSetAttribute(mm_bf16<22>, cudaFuncAttributeMaxDynamicSharedMemorySize, SMEM_MM);
    cudaFuncSetAttribute(flash_kernel, cudaFuncAttributeMaxDynamicSharedMemorySize, SMEM_FL);

    // mask bits
    packmask_kernel<<<BB*TT*TT/256, 256>>>(mask, mb);

    // weight transforms
    {
        dim3 blk(32, 8);
        wsplit_kernel<<<dim3(DD/32, DD/32), blk>>>(wq, wqkvT, DD, DD);
        wsplit_kernel<<<dim3(DD/32, DD/32), blk>>>(wk, wqkvT + (size_t)DD*K3D, DD, DD);
        wsplit_kernel<<<dim3(DD/32, DD/32), blk>>>(wv, wqkvT + 2*(size_t)DD*K3D, DD, DD);
        wsplit_kernel<<<dim3(DD/32, DD/32), blk>>>(w_proj, wpT, DD, DD);
        wsplit_kernel<<<dim3(FF/32, DD/32), blk>>>(w1, w1T, DD, FF);
        wsplit_kernel<<<dim3(DD/32, FF/32), blk>>>(w2, w2T, FF, DD);
    }

    // LN1 -> split
    ln_split_kernel<<<NROWS, 256>>>(x, ln1_g, ln1_b, hs);

    // fused QKV GEMM (grid.z selects q/k/v)
    mm_bf16<0><<<dim3(DD/128, NROWS/128, 3), 256, SMEM_MM>>>(
        hs, wqkvT, nullptr, nullptr, qkv, nullptr, DD, K3D,
        (long)DD*K3D, (long)NROWS*DD);

    // RoPE on q, k
    {
        int total = BB*TT*HH*32;
        rope_kernel<<<(total + 255)/256, 256>>>(qkv);
        rope_kernel<<<(total + 255)/256, 256>>>(qkv + (size_t)NROWS*DD);
    }

    // flash attention -> split att
    flash_kernel<<<dim3(TT/64, NBH), 128, SMEM_FL>>>(
        qkv, qkv + (size_t)NROWS*DD, qkv + 2*(size_t)NROWS*DD, mb, atts);

    // proj + bias + residual
    mm_bf16<10><<<dim3(DD/128, NROWS/128), 256, SMEM_MM>>>(
        atts, wpT, b_proj, x, x2_, nullptr, DD, K3D, 0L, 0L);

    // LN2 -> split
    ln_split_kernel<<<NROWS, 256>>>(x2_, ln2_g, ln2_b, h2s);

    // MLP1: bias + relu + split out
    mm_bf16<22><<<dim3(FF/128, NROWS/128), 256, SMEM_MM>>>(
        h2s, w1T, b1, nullptr, nullptr, ffs, FF, K3D, 0L, 0L);

    // MLP2: bias + residual -> out
    mm_bf16<10><<<dim3(DD/128, NROWS/128), 256, SMEM_MM>>>(
        ffs, w2T, b2, x2_, out, nullptr, DD, K3F, 0L, 0L);
}

// round 5
// speedup vs baseline: 9.6889x; 2.2242x over previous
#include <cuda_runtime.h>
#include <cuda_fp16.h>
#include <cstdint>
#include <math.h>

#define BB 2
#define TT 2048
#define DD 1024
#define HH 16
#define FF 4096
#define NROWS (BB*TT)
#define NBH (BB*HH)

// ================= scratch =================
__device__ __align__(256) __half  g_h16 [NROWS*DD];
__device__ __align__(256) __half  g_qkv [3*(size_t)NROWS*DD];
__device__ __align__(256) __half  g_att [NROWS*DD];
__device__ __align__(256) float   g_x2  [NROWS*DD];
__device__ __align__(256) __half  g_h216[NROWS*DD];
__device__ __align__(256) __half  g_ff  [(size_t)NROWS*FF];
__device__ __align__(256) __half  g_wqkvT[3*(size_t)DD*DD];
__device__ __align__(256) __half  g_wpT [(size_t)DD*DD];
__device__ __align__(256) __half  g_w1T [(size_t)FF*DD];
__device__ __align__(256) __half  g_w2T [(size_t)DD*FF];
__device__ __align__(256) uint32_t g_mb [BB*TT*(TT/32)];
__device__ __align__(256) float2  g_rt  [TT*32];

// ================= helpers =================
__device__ __forceinline__ uint32_t smem_u32(const void* p) {
    uint32_t a;
    asm("{ .reg .u64 t; cvta.to.shared.u64 t, %1; cvt.u32.u64 %0, t; }" : "=r"(a) : "l"(p));
    return a;
}
#define CPA(dst, src) \
    asm volatile("cp.async.cg.shared.global [%0], [%1], 16;" :: "r"(dst), "l"(src) : "memory")
#define CPCOMMIT asm volatile("cp.async.commit_group;" ::: "memory")
#define CPWAIT(n) asm volatile("cp.async.wait_group %0;" :: "n"(n) : "memory")

__device__ __forceinline__ void ldsm4(uint32_t& r0, uint32_t& r1, uint32_t& r2, uint32_t& r3, uint32_t a) {
    asm volatile("ldmatrix.sync.aligned.m8n8.x4.shared.b16 {%0,%1,%2,%3}, [%4];"
        : "=r"(r0), "=r"(r1), "=r"(r2), "=r"(r3) : "r"(a));
}
__device__ __forceinline__ void ldsm4t(uint32_t& r0, uint32_t& r1, uint32_t& r2, uint32_t& r3, uint32_t a) {
    asm volatile("ldmatrix.sync.aligned.m8n8.x4.trans.shared.b16 {%0,%1,%2,%3}, [%4];"
        : "=r"(r0), "=r"(r1), "=r"(r2), "=r"(r3) : "r"(a));
}
__device__ __forceinline__ void mma_f16(float* c, const uint32_t* a, uint32_t b0, uint32_t b1) {
    asm volatile("mma.sync.aligned.m16n8k16.row.col.f32.f16.f16.f32 "
        "{%0,%1,%2,%3}, {%4,%5,%6,%7}, {%8,%9}, {%0,%1,%2,%3};"
        : "+f"(c[0]), "+f"(c[1]), "+f"(c[2]), "+f"(c[3])
        : "r"(a[0]), "r"(a[1]), "r"(a[2]), "r"(a[3]), "r"(b0), "r"(b1));
}

// ================= LayerNorm -> fp16 =================
__global__ void ln16_kernel(const float* __restrict__ x, const float* __restrict__ g,
                            const float* __restrict__ b, __half* __restrict__ out) {
    int row = blockIdx.x;
    const float* xr = x + (size_t)row * DD;
    __shared__ float sm[256];
    int tid = threadIdx.x;

    float s = 0.f;
    for (int i = tid; i < DD; i += 256) s += xr[i];
    sm[tid] = s; __syncthreads();
    for (int o = 128; o > 0; o >>= 1) { if (tid < o) sm[tid] += sm[tid+o]; __syncthreads(); }
    float mean = sm[0] * (1.0f / DD);
    __syncthreads();
    float v = 0.f;
    for (int i = tid; i < DD; i += 256) { float d = xr[i] - mean; v += d * d; }
    sm[tid] = v; __syncthreads();
    for (int o = 128; o > 0; o >>= 1) { if (tid < o) sm[tid] += sm[tid+o]; __syncthreads(); }
    float inv = rsqrtf(sm[0] * (1.0f / DD) + 1e-5f);

    __half* orow = out + (size_t)row * DD;
    for (int i = tid; i < DD; i += 256)
        orow[i] = __float2half_rn((xr[i] - mean) * inv * g[i] + b[i]);
}

// ================= weight transpose: W[K,N] fp32 -> out[N][K] fp16 =================
__global__ void wt16_kernel(const float* __restrict__ W, __half* __restrict__ out,
                            int K, int N) {
    __shared__ float t[32][33];
    int k0 = blockIdx.y * 32, n0 = blockIdx.x * 32;
    int tx = threadIdx.x, ty = threadIdx.y;   // 32 x 8
#pragma unroll
    for (int r = 0; r < 4; r++)
        t[ty + 8*r][tx] = W[(size_t)(k0 + ty + 8*r) * N + n0 + tx];
    __syncthreads();
#pragma unroll
    for (int r = 0; r < 4; r++)
        out[(size_t)(n0 + ty + 8*r) * K + k0 + tx] = __float2half_rn(t[tx][ty + 8*r]);
}

// ================= rope table: [t][pair] -> (cos, sin) =================
__global__ void ropetab_kernel(float2* __restrict__ rt) {
    int idx = blockIdx.x * 256 + threadIdx.x;
    if (idx >= TT*32) return;
    int t = idx >> 5, pi = idx & 31;
    float theta = expf(-((2.0f * pi) / 64.0f) * logf(10000.0f));
    float ang = (float)t * theta;
    rt[idx] = make_float2(cosf(ang), sinf(ang));
}

// ================= pack mask to bits =================
__global__ void packmask_kernel(const int* __restrict__ mask, uint32_t* __restrict__ mb) {
    int idx = blockIdx.x * 256 + threadIdx.x;
    uint32_t w = __ballot_sync(0xffffffffu, mask[idx] != 0);
    if ((threadIdx.x & 31) == 0) mb[idx >> 5] = w;
}

// ================= mma.sync fp16 GEMM: C[M,N] = A[M,K] . Bw[N,K]^T =================
// EPI bits: 1=ROPE(z<2), 2=BIAS, 4=RELU, 8=RES, 16=F16OUT
template<int EPI>
__global__ void __launch_bounds__(256) mm16(
        const __half* __restrict__ A, const __half* __restrict__ B0,
        const float* __restrict__ bias, const float* __restrict__ res,
        float* __restrict__ outF, __half* __restrict__ outH0,
        int N, int K, long zsB, long zsC, const float2* __restrict__ rt) {
    extern __shared__ char smem_raw[];
    const uint32_t sbr = smem_u32(smem_raw);
    const uint32_t sb = (sbr + 1023) & ~1023u;

    const int tid = threadIdx.x, wid = tid >> 5, lane = tid & 31;
    const int wm = wid >> 1, wn = wid & 1;
    const int m0 = blockIdx.y << 7, n0 = blockIdx.x << 7;
    const int NC = K >> 6;

    const __half* Bw = B0 + (size_t)blockIdx.z * zsB;
    __half* outH = outH0 + (size_t)blockIdx.z * zsC;

    const __half* Ag = A  + (size_t)m0 * K;
    const __half* Bg = Bw + (size_t)n0 * K;

    const int rq_r = tid >> 3, rq_q = tid & 7;
    const __half* agp = Ag + (size_t)rq_r * K + (rq_q << 3);
    const __half* bgp = Bg + (size_t)rq_r * K + (rq_q << 3);
    uint32_t so = (uint32_t)((rq_r << 7) + (rq_q << 4));
    so ^= (so >> 3) & 0x70;
    const size_t rowstep = (size_t)32 * K;

    auto issue_load = [&](int c, int stg) {
        uint32_t sA = sb + stg * 32768;
#pragma unroll
        for (int v = 0; v < 4; v++) {
            CPA(sA + so + v*4096,         agp + (size_t)c*64 + v*rowstep);
            CPA(sA + 16384 + so + v*4096, bgp + (size_t)c*64 + v*rowstep);
        }
    };

    float acc[2][8][4];
#pragma unroll
    for (int mi = 0; mi < 2; mi++)
#pragma unroll
        for (int ni = 0; ni < 8; ni++)
#pragma unroll
            for (int v = 0; v < 4; v++) acc[mi][ni][v] = 0.f;

#pragma unroll
    for (int s = 0; s < 3; s++) { issue_load(s, s); CPCOMMIT; }

    for (int c = 0; c < NC; c++) {
        CPWAIT(2);
        __syncthreads();
        int stg = c % 3;
        uint32_t sA = sb + stg * 32768;
        uint32_t sB = sA + 16384;
#pragma unroll
        for (int kk = 0; kk < 4; kk++) {
            uint32_t a[2][4], b0[8], b1[8];
            const int kb = kk*32 + ((lane >> 4) << 4);
#pragma unroll
            for (int mi = 0; mi < 2; mi++) {
                int row = wm*32 + mi*16 + (lane & 15);
                uint32_t o = (uint32_t)(row*128 + kb); o ^= (o >> 3) & 0x70;
                ldsm4(a[mi][0], a[mi][1], a[mi][2], a[mi][3], sA + o);
            }
#pragma unroll
            for (int j = 0; j < 4; j++) {
                int row = wn*64 + j*16 + (lane & 15);
                uint32_t o = (uint32_t)(row*128 + kb); o ^= (o >> 3) & 0x70;
                ldsm4(b0[2*j], b0[2*j+1], b1[2*j], b1[2*j+1], sB + o);
            }
#pragma unroll
            for (int mi = 0; mi < 2; mi++)
#pragma unroll
                for (int ni = 0; ni < 8; ni++)
                    mma_f16(acc[mi][ni], a[mi], b0[ni], b1[ni]);
        }
        __syncthreads();
        if (c + 3 < NC) issue_load(c + 3, stg);
        CPCOMMIT;
    }
    CPWAIT(0);

    // epilogue
    const int g = lane >> 2, tq = lane & 3;
    const bool doRope = (EPI & 1) && (blockIdx.z < 2);
#pragma unroll
    for (int mi = 0; mi < 2; mi++) {
#pragma unroll
        for (int ni = 0; ni < 8; ni++) {
            const int colb = n0 + wn*64 + ni*8 + 2*tq;
            float2 bv = make_float2(0.f, 0.f);
            if (EPI & 2) bv = *(const float2*)(bias + colb);
#pragma unroll
            for (int rh = 0; rh < 2; rh++) {
                int row = m0 + wm*32 + mi*16 + g + rh*8;
                float v0 = acc[mi][ni][rh*2], v1 = acc[mi][ni][rh*2+1];
                if (EPI & 2) { v0 += bv.x; v1 += bv.y; }
                if (EPI & 4) { v0 = fmaxf(v0, 0.f); v1 = fmaxf(v1, 0.f); }
                if (doRope) {
                    int t = row & (TT-1);
                    int pi = (colb & 63) >> 1;
                    float2 cs = rt[t*32 + pi];
                    float nv0 = v0*cs.x - v1*cs.y;
                    float nv1 = v0*cs.y + v1*cs.x;
                    v0 = nv0; v1 = nv1;
                }
                if (EPI & 8) {
                    float2 rv = *(const float2*)(res + (size_t)row*N + colb);
                    v0 += rv.x; v1 += rv.y;
                }
                if (EPI & 16) {
                    __half2 hv = __floats2half2_rn(v0, v1);
                    *(__half2*)(outH + (size_t)row*N + colb) = hv;
                } else {
                    *(float2*)(outF + (size_t)row*N + colb) = make_float2(v0, v1);
                }
            }
        }
    }
}

// ================= flash attention: fp16 in/out, 128-row Q tiles =================
__global__ void __launch_bounds__(256) flash_kernel(
        const __half* __restrict__ qg, const __half* __restrict__ kg, const __half* __restrict__ vg,
        const uint32_t* __restrict__ mb, __half* __restrict__ attH) {
    extern __shared__ char smem_raw[];
    const uint32_t sbr = smem_u32(smem_raw);
    const uint32_t sb = (sbr + 1023) & ~1023u;
    char* base = smem_raw + (int)(sb - sbr);

    const uint32_t sQ = sb, sK = sb + 16384, sV = sb + 32768, sP = sb + 49152;

    int bh = blockIdx.y, b = bh >> 4, h = bh & 15;
    int t0 = blockIdx.x << 7;
    int tid = threadIdx.x, wid = tid >> 5, lane = tid & 31;
    int g = lane >> 2, tq = lane & 3;

    const __half* kbase = kg + ((size_t)(b*TT)) * DD + h*64;
    const __half* vbase = vg + ((size_t)(b*TT)) * DD + h*64;

    // per-thread K/V cp.async mapping: 2 uint4 each per stage
    const int lr = tid >> 3, lq = tid & 7;      // row 0..31, 16B col 0..7
    uint32_t lso = (uint32_t)((lr << 7) + (lq << 4));
    lso ^= (lso >> 3) & 0x70;

    auto issue_kv = [&](int s0, int stg) {
        const __half* ks = kbase + (size_t)s0 * DD;
        const __half* vs = vbase + (size_t)s0 * DD;
#pragma unroll
        for (int v = 0; v < 2; v++) {
            CPA(sK + stg*8192 + lso + v*4096, ks + (size_t)(lr + v*32)*DD + lq*8);
            CPA(sV + stg*8192 + lso + v*4096, vs + (size_t)(lr + v*32)*DD + lq*8);
        }
    };

    issue_kv(0, 0); CPCOMMIT;

    // load Q tile (128 rows, swizzled)
    {
        const __half* src = qg + ((size_t)(b*TT) + t0) * DD + h*64;
#pragma unroll
        for (int v = 0; v < 4; v++) {
            int p = tid + (v << 8);
            int t = p >> 3, dq = p & 7;
            uint32_t o = (uint32_t)(t*128 + dq*16); o ^= (o >> 3) & 0x70;
            *(uint4*)(base + o) = *(const uint4*)(src + (size_t)t*DD + dq*8);
        }
    }

    float mrow[2] = {-1e30f, -1e30f};
    float lrow[2] = {0.f, 0.f};
    float o[8][4];
#pragma unroll
    for (int ni = 0; ni < 8; ni++)
#pragma unroll
        for (int v = 0; v < 4; v++) o[ni][v] = 0.f;

    const int NS = TT / 64;
    for (int i = 0; i < NS; i++) {
        if (i + 1 < NS) { issue_kv((i+1)*64, (i+1) & 1); CPCOMMIT; CPWAIT(1); }
        else            { CPWAIT(0); }
        __syncthreads();
        const uint32_t kS = sK + (i & 1)*8192;
        const uint32_t vS = sV + (i & 1)*8192;
        const int s0 = i * 64;

        // S = Q K^T
        float sa[8][4];
#pragma unroll
        for (int ni = 0; ni < 8; ni++)
#pragma unroll
            for (int v = 0; v < 4; v++) sa[ni][v] = 0.f;
#pragma unroll
        for (int kk = 0; kk < 4; kk++) {
            const int kb = kk*32 + ((lane >> 4) << 4);
            uint32_t a[4], b0[8], b1[8];
            {
                int row = wid*16 + (lane & 15);
                uint32_t oo = (uint32_t)(row*128 + kb); oo ^= (oo >> 3) & 0x70;
                ldsm4(a[0], a[1], a[2], a[3], sQ + oo);
            }
#pragma unroll
            for (int j = 0; j < 4; j++) {
                int row = j*16 + (lane & 15);
                uint32_t oo = (uint32_t)(row*128 + kb); oo ^= (oo >> 3) & 0x70;
                ldsm4(b0[2*j], b0[2*j+1], b1[2*j], b1[2*j+1], kS + oo);
            }
#pragma unroll
            for (int ni = 0; ni < 8; ni++) mma_f16(sa[ni], a, b0[ni], b1[ni]);
        }

        // mask + scale (bit-packed mask straight from global/L1)
        {
            int tr0 = t0 + wid*16 + g;
            const uint32_t* mrow0 = mb + ((size_t)(b*TT) + tr0)*(TT/32) + (s0 >> 5);
            const uint32_t* mrow1 = mrow0 + 8*(TT/32);
            uint32_t w00 = mrow0[0], w01 = mrow0[1];
            uint32_t w10 = mrow1[0], w11 = mrow1[1];
#pragma unroll
            for (int ni = 0; ni < 8; ni++) {
#pragma unroll
                for (int v = 0; v < 4; v++) {
                    int sc = ni*8 + 2*tq + (v & 1);
                    uint32_t wsel = (v < 2) ? ((sc < 32) ? w00 : w01)
                                            : ((sc < 32) ? w10 : w11);
                    bool ok = (wsel >> (sc & 31)) & 1u;
                    sa[ni][v] = ok ? sa[ni][v]*0.125f : -1e30f;
                }
            }
        }

        // online softmax
#pragma unroll
        for (int rh = 0; rh < 2; rh++) {
            float mx = -1e30f;
#pragma unroll
            for (int ni = 0; ni < 8; ni++)
                mx = fmaxf(mx, fmaxf(sa[ni][rh*2], sa[ni][rh*2+1]));
            mx = fmaxf(mx, __shfl_xor_sync(0xffffffffu, mx, 1));
            mx = fmaxf(mx, __shfl_xor_sync(0xffffffffu, mx, 2));
            float mn = fmaxf(mrow[rh], mx);
            float alpha = __expf(mrow[rh] - mn);
            mrow[rh] = mn;
            float rs = 0.f;
#pragma unroll
            for (int ni = 0; ni < 8; ni++) {
                float p0 = __expf(sa[ni][rh*2]   - mn);
                float p1 = __expf(sa[ni][rh*2+1] - mn);
                sa[ni][rh*2] = p0; sa[ni][rh*2+1] = p1;
                rs += p0 + p1;
            }
            rs += __shfl_xor_sync(0xffffffffu, rs, 1);
            rs += __shfl_xor_sync(0xffffffffu, rs, 2);
            lrow[rh] = lrow[rh]*alpha + rs;
#pragma unroll
            for (int ni = 0; ni < 8; ni++) { o[ni][rh*2] *= alpha; o[ni][rh*2+1] *= alpha; }
        }

        // P -> smem fp16 (own warp rows only)
#pragma unroll
        for (int ni = 0; ni < 8; ni++) {
#pragma unroll
            for (int rh = 0; rh < 2; rh++) {
                int trow = wid*16 + g + rh*8;
                int scol = ni*8 + 2*tq;
                __half2 hp = __floats2half2_rn(sa[ni][rh*2], sa[ni][rh*2+1]);
                uint32_t oo = (uint32_t)(trow*128 + scol*2); oo ^= (oo >> 3) & 0x70;
                *(uint32_t*)(base + (sP - sb) + oo) = *(uint32_t*)&hp;
            }
        }
        __syncwarp();

        // O += P V
#pragma unroll
        for (int kk = 0; kk < 4; kk++) {
            uint32_t a[4], b0[8], b1[8];
            {
                int row = wid*16 + (lane & 15);
                uint32_t oo = (uint32_t)(row*128 + kk*32 + ((lane >> 4) << 4));
                oo ^= (oo >> 3) & 0x70;
                ldsm4(a[0], a[1], a[2], a[3], sP + oo);
            }
#pragma unroll
            for (int j = 0; j < 4; j++) {
                int rs_ = kk*16 + (lane & 15);
                uint32_t oo = (uint32_t)(rs_*128 + j*32 + ((lane >> 4) << 4));
                oo ^= (oo >> 3) & 0x70;
                ldsm4t(b0[2*j], b1[2*j], b0[2*j+1], b1[2*j+1], vS + oo);
            }
#pragma unroll
            for (int ni = 0; ni < 8; ni++) mma_f16(o[ni], a, b0[ni], b1[ni]);
        }
        __syncthreads();
    }

    // write att (fp16)
#pragma unroll
    for (int rh = 0; rh < 2; rh++) {
        float inv = 1.0f / lrow[rh];
        int t = t0 + wid*16 + g + rh*8;
        size_t rb = ((size_t)(b*TT) + t) * DD;
#pragma unroll
        for (int ni = 0; ni < 8; ni++) {
            int col = h*64 + ni*8 + 2*tq;
            __half2 hv = __floats2half2_rn(o[ni][rh*2] * inv, o[ni][rh*2+1] * inv);
            *(__half2*)(attH + rb + col) = hv;
        }
    }
}

// ================= launch =================
template<typename T>
static T* symaddr(const void* sym) {
    void* p = nullptr;
    cudaGetSymbolAddress(&p, sym);
    return (T*)p;
}

extern "C" void kernel_launch(void* const* d_in, const int* in_sizes, int n_in,
                              void* d_out, int out_size) {
    const float* x      = (const float*)d_in[0];
    const int*   mask   = (const int*)  d_in[1];
    const float* wq     = (const float*)d_in[2];
    const float* wk     = (const float*)d_in[3];
    const float* wv     = (const float*)d_in[4];
    const float* w_proj = (const float*)d_in[5];
    const float* b_proj = (const float*)d_in[6];
    const float* ln1_g  = (const float*)d_in[7];
    const float* ln1_b  = (const float*)d_in[8];
    const float* ln2_g  = (const float*)d_in[9];
    const float* ln2_b  = (const float*)d_in[10];
    const float* w1     = (const float*)d_in[11];
    const float* b1     = (const float*)d_in[12];
    const float* w2     = (const float*)d_in[13];
    const float* b2     = (const float*)d_in[14];
    float* out = (float*)d_out;

    __half* h16   = symaddr<__half>(g_h16);
    __half* qkv   = symaddr<__half>(g_qkv);
    __half* att   = symaddr<__half>(g_att);
    float*  x2_   = symaddr<float>(g_x2);
    __half* h216  = symaddr<__half>(g_h216);
    __half* ff    = symaddr<__half>(g_ff);
    __half* wqkvT = symaddr<__half>(g_wqkvT);
    __half* wpT   = symaddr<__half>(g_wpT);
    __half* w1T   = symaddr<__half>(g_w1T);
    __half* w2T   = symaddr<__half>(g_w2T);
    uint32_t* mb  = symaddr<uint32_t>(g_mb);
    float2* rt    = symaddr<float2>(g_rt);

    const int SMEM_MM = 3*32768 + 1024;   // 99328
    const int SMEM_FL = 4*16384 + 1024;   // 66560
    cudaFuncSetAttribute(mm16<17>, cudaFuncAttributeMaxDynamicSharedMemorySize, SMEM_MM);
    cudaFuncSetAttribute(mm16<10>, cudaFuncAttributeMaxDynamicSharedMemorySize, SMEM_MM);
    cudaFuncSetAttribute(mm16<22>, cudaFuncAttributeMaxDynamicSharedMemorySize, SMEM_MM);
    cudaFuncSetAttribute(flash_kernel, cudaFuncAttributeMaxDynamicSharedMemorySize, SMEM_FL);

    packmask_kernel<<<BB*TT*TT/256, 256>>>(mask, mb);
    ropetab_kernel<<<(TT*32 + 255)/256, 256>>>(rt);

    {
        dim3 blk(32, 8);
        wt16_kernel<<<dim3(DD/32, DD/32), blk>>>(wq, wqkvT, DD, DD);
        wt16_kernel<<<dim3(DD/32, DD/32), blk>>>(wk, wqkvT + (size_t)DD*DD, DD, DD);
        wt16_kernel<<<dim3(DD/32, DD/32), blk>>>(wv, wqkvT + 2*(size_t)DD*DD, DD, DD);
        wt16_kernel<<<dim3(DD/32, DD/32), blk>>>(w_proj, wpT, DD, DD);
        wt16_kernel<<<dim3(FF/32, DD/32), blk>>>(w1, w1T, DD, FF);
        wt16_kernel<<<dim3(DD/32, FF/32), blk>>>(w2, w2T, FF, DD);
    }

    // LN1 -> fp16
    ln16_kernel<<<NROWS, 256>>>(x, ln1_g, ln1_b, h16);

    // fused QKV GEMM, RoPE in epilogue for z<2, fp16 out
    mm16<17><<<dim3(DD/128, NROWS/128, 3), 256, SMEM_MM>>>(
        h16, wqkvT, nullptr, nullptr, nullptr, qkv, DD, DD,
        (long)DD*DD, (long)NROWS*DD, rt);

    // flash attention
    flash_kernel<<<dim3(TT/128, NBH), 256, SMEM_FL>>>(
        qkv, qkv + (size_t)NROWS*DD, qkv + 2*(size_t)NROWS*DD, mb, att);

    // proj + bias + residual -> x2 (fp32)
    mm16<10><<<dim3(DD/128, NROWS/128), 256, SMEM_MM>>>(
        att, wpT, b_proj, x, x2_, nullptr, DD, DD, 0L, 0L, rt);

    // LN2 -> fp16
    ln16_kernel<<<NROWS, 256>>>(x2_, ln2_g, ln2_b, h216);

    // MLP1: bias + relu -> fp16
    mm16<22><<<dim3(FF/128, NROWS/128), 256, SMEM_MM>>>(
        h216, w1T, b1, nullptr, nullptr, ff, FF, DD, 0L, 0L, rt);

    // MLP2: bias + residual -> out (fp32)
    mm16<10><<<dim3(DD/128, NROWS/128), 256, SMEM_MM>>>(
        ff, w2T, b2, x2_, out, nullptr, DD, FF, 0L, 0L, rt);
}

// round 6
// speedup vs baseline: 11.0531x; 1.1408x over previous
#include <cuda_runtime.h>
#include <cuda_fp16.h>
#include <cstdint>
#include <math.h>

#define BB 2
#define TT 2048
#define DD 1024
#define HH 16
#define FF 4096
#define NROWS (BB*TT)
#define NBH (BB*HH)

// ================= scratch =================
__device__ __align__(256) __half  g_h16 [NROWS*DD];
__device__ __align__(256) __half  g_qkv [3*(size_t)NROWS*DD];
__device__ __align__(256) __half  g_att [NROWS*DD];
__device__ __align__(256) float   g_x2  [NROWS*DD];
__device__ __align__(256) __half  g_h216[NROWS*DD];
__device__ __align__(256) __half  g_ff  [(size_t)NROWS*FF];
__device__ __align__(256) __half  g_wqkvT[3*(size_t)DD*DD];
__device__ __align__(256) __half  g_wpT [(size_t)DD*DD];
__device__ __align__(256) __half  g_w1T [(size_t)FF*DD];
__device__ __align__(256) __half  g_w2T [(size_t)DD*FF];
__device__ __align__(256) uint32_t g_mb [BB*TT*(TT/32)];
__device__ __align__(256) int      g_mf [BB*32];
__device__ __align__(256) float2  g_rt  [TT*32];

// ================= helpers =================
__device__ __forceinline__ uint32_t smem_u32(const void* p) {
    uint32_t a;
    asm("{ .reg .u64 t; cvta.to.shared.u64 t, %1; cvt.u32.u64 %0, t; }" : "=r"(a) : "l"(p));
    return a;
}
#define CPA(dst, src) \
    asm volatile("cp.async.cg.shared.global [%0], [%1], 16;" :: "r"(dst), "l"(src) : "memory")
#define CPCOMMIT asm volatile("cp.async.commit_group;" ::: "memory")
#define CPWAIT(n) asm volatile("cp.async.wait_group %0;" :: "n"(n) : "memory")

__device__ __forceinline__ void ldsm4(uint32_t& r0, uint32_t& r1, uint32_t& r2, uint32_t& r3, uint32_t a) {
    asm volatile("ldmatrix.sync.aligned.m8n8.x4.shared.b16 {%0,%1,%2,%3}, [%4];"
        : "=r"(r0), "=r"(r1), "=r"(r2), "=r"(r3) : "r"(a));
}
__device__ __forceinline__ void ldsm4t(uint32_t& r0, uint32_t& r1, uint32_t& r2, uint32_t& r3, uint32_t a) {
    asm volatile("ldmatrix.sync.aligned.m8n8.x4.trans.shared.b16 {%0,%1,%2,%3}, [%4];"
        : "=r"(r0), "=r"(r1), "=r"(r2), "=r"(r3) : "r"(a));
}
__device__ __forceinline__ void mma_f16(float* c, const uint32_t* a, uint32_t b0, uint32_t b1) {
    asm volatile("mma.sync.aligned.m16n8k16.row.col.f32.f16.f16.f32 "
        "{%0,%1,%2,%3}, {%4,%5,%6,%7}, {%8,%9}, {%0,%1,%2,%3};"
        : "+f"(c[0]), "+f"(c[1]), "+f"(c[2]), "+f"(c[3])
        : "r"(a[0]), "r"(a[1]), "r"(a[2]), "r"(a[3]), "r"(b0), "r"(b1));
}

// ================= LayerNorm -> fp16 (vectorized) =================
__global__ void ln16_kernel(const float* __restrict__ x, const float* __restrict__ g,
                            const float* __restrict__ b, __half* __restrict__ out) {
    int row = blockIdx.x;
    int tid = threadIdx.x;
    const float4 f = ((const float4*)(x + (size_t)row * DD))[tid];
    __shared__ float sw[8];
    int wid = tid >> 5, lane = tid & 31;

    float s = f.x + f.y + f.z + f.w;
#pragma unroll
    for (int o = 16; o; o >>= 1) s += __shfl_xor_sync(~0u, s, o);
    if (lane == 0) sw[wid] = s;
    __syncthreads();
    s = sw[lane & 7];
#pragma unroll
    for (int o = 4; o; o >>= 1) s += __shfl_xor_sync(~0u, s, o);
    float mean = s * (1.0f / DD);

    float dx = f.x - mean, dy = f.y - mean, dz = f.z - mean, dw = f.w - mean;
    float v = dx*dx + dy*dy + dz*dz + dw*dw;
#pragma unroll
    for (int o = 16; o; o >>= 1) v += __shfl_xor_sync(~0u, v, o);
    __syncthreads();
    if (lane == 0) sw[wid] = v;
    __syncthreads();
    v = sw[lane & 7];
#pragma unroll
    for (int o = 4; o; o >>= 1) v += __shfl_xor_sync(~0u, v, o);
    float inv = rsqrtf(v * (1.0f / DD) + 1e-5f);

    const float4 g4 = ((const float4*)g)[tid];
    const float4 b4 = ((const float4*)b)[tid];
    __half2 h0 = __floats2half2_rn(dx*inv*g4.x + b4.x, dy*inv*g4.y + b4.y);
    __half2 h1 = __floats2half2_rn(dz*inv*g4.z + b4.z, dw*inv*g4.w + b4.w);
    uint2 st; st.x = *(uint32_t*)&h0; st.y = *(uint32_t*)&h1;
    *(uint2*)(out + (size_t)row * DD + tid*4) = st;
}

// ================= weight transpose: W[K,N] fp32 -> out[N][K] fp16 =================
__global__ void wt16_kernel(const float* __restrict__ W, __half* __restrict__ out,
                            int K, int N) {
    __shared__ float t[32][33];
    int k0 = blockIdx.y * 32, n0 = blockIdx.x * 32;
    int tx = threadIdx.x, ty = threadIdx.y;   // 32 x 8
#pragma unroll
    for (int r = 0; r < 4; r++)
        t[ty + 8*r][tx] = W[(size_t)(k0 + ty + 8*r) * N + n0 + tx];
    __syncthreads();
#pragma unroll
    for (int r = 0; r < 4; r++)
        out[(size_t)(n0 + ty + 8*r) * K + k0 + tx] = __float2half_rn(t[tx][ty + 8*r]);
}

// ================= rope table =================
__global__ void ropetab_kernel(float2* __restrict__ rt) {
    int idx = blockIdx.x * 256 + threadIdx.x;
    if (idx >= TT*32) return;
    int t = idx >> 5, pi = idx & 31;
    float theta = expf(-((2.0f * pi) / 64.0f) * logf(10000.0f));
    float ang = (float)t * theta;
    rt[idx] = make_float2(cosf(ang), sinf(ang));
}

// ================= pack mask to bits =================
__global__ void packmask_kernel(const int* __restrict__ mask, uint32_t* __restrict__ mb) {
    int idx = blockIdx.x * 256 + threadIdx.x;
    uint32_t w = __ballot_sync(0xffffffffu, mask[idx] != 0);
    if ((threadIdx.x & 31) == 0) mb[idx >> 5] = w;
}

// ================= per-(b, key-block) all/any flags =================
__global__ void maskflags_kernel(const uint32_t* __restrict__ mb, int* __restrict__ mf) {
    int bs = blockIdx.x;                 // b*32 + sblk
    int b = bs >> 5, sblk = bs & 31;
    uint32_t av = 0xFFFFFFFFu, ov = 0u;
    for (int t = threadIdx.x; t < TT; t += 256) {
        const uint32_t* p = mb + ((size_t)(b*TT) + t)*(TT/32) + sblk*2;
        uint32_t w0 = p[0], w1 = p[1];
        av &= (w0 & w1); ov |= (w0 | w1);
    }
    __shared__ uint32_t sa[8], so[8];
#pragma unroll
    for (int o = 16; o; o >>= 1) {
        av &= __shfl_xor_sync(~0u, av, o);
        ov |= __shfl_xor_sync(~0u, ov, o);
    }
    int w = threadIdx.x >> 5;
    if ((threadIdx.x & 31) == 0) { sa[w] = av; so[w] = ov; }
    __syncthreads();
    if (threadIdx.x == 0) {
        av = 0xFFFFFFFFu; ov = 0u;
#pragma unroll
        for (int i = 0; i < 8; i++) { av &= sa[i]; ov |= so[i]; }
        mf[bs] = ((av == 0xFFFFFFFFu) ? 2 : 0) | (ov ? 1 : 0);
    }
}

// ================= mma.sync fp16 GEMM (2-stage, 2 CTA/SM) =================
// EPI bits: 1=ROPE(z<2), 2=BIAS, 4=RELU, 8=RES, 16=F16OUT, 32=QSCALE(z==0)
template<int EPI>
__global__ void __launch_bounds__(256, 2) mm16(
        const __half* __restrict__ A, const __half* __restrict__ B0,
        const float* __restrict__ bias, const float* __restrict__ res,
        float* __restrict__ outF, __half* __restrict__ outH0,
        int N, int K, long zsB, long zsC, const float2* __restrict__ rt) {
    extern __shared__ char smem_raw[];
    const uint32_t sbr = smem_u32(smem_raw);
    const uint32_t sb = (sbr + 1023) & ~1023u;

    const int tid = threadIdx.x, wid = tid >> 5, lane = tid & 31;
    const int wm = wid >> 1, wn = wid & 1;
    const int m0 = blockIdx.y << 7, n0 = blockIdx.x << 7;
    const int NC = K >> 6;

    const __half* Bw = B0 + (size_t)blockIdx.z * zsB;
    __half* outH = outH0 + (size_t)blockIdx.z * zsC;

    const __half* Ag = A  + (size_t)m0 * K;
    const __half* Bg = Bw + (size_t)n0 * K;

    const int rq_r = tid >> 3, rq_q = tid & 7;
    const __half* agp = Ag + (size_t)rq_r * K + (rq_q << 3);
    const __half* bgp = Bg + (size_t)rq_r * K + (rq_q << 3);
    uint32_t so = (uint32_t)((rq_r << 7) + (rq_q << 4));
    so ^= (so >> 3) & 0x70;
    const size_t rowstep = (size_t)32 * K;

    auto issue_load = [&](int c, int stg) {
        uint32_t sA = sb + stg * 32768;
#pragma unroll
        for (int v = 0; v < 4; v++) {
            CPA(sA + so + v*4096,         agp + (size_t)c*64 + v*rowstep);
            CPA(sA + 16384 + so + v*4096, bgp + (size_t)c*64 + v*rowstep);
        }
    };

    float acc[2][8][4];
#pragma unroll
    for (int mi = 0; mi < 2; mi++)
#pragma unroll
        for (int ni = 0; ni < 8; ni++)
#pragma unroll
            for (int v = 0; v < 4; v++) acc[mi][ni][v] = 0.f;

#pragma unroll
    for (int s = 0; s < 2; s++) { issue_load(s, s); CPCOMMIT; }

    for (int c = 0; c < NC; c++) {
        CPWAIT(1);
        __syncthreads();
        int stg = c & 1;
        uint32_t sA = sb + stg * 32768;
        uint32_t sB = sA + 16384;
#pragma unroll
        for (int kk = 0; kk < 4; kk++) {
            uint32_t a[2][4], b0[8], b1[8];
            const int kb = kk*32 + ((lane >> 4) << 4);
#pragma unroll
            for (int mi = 0; mi < 2; mi++) {
                int row = wm*32 + mi*16 + (lane & 15);
                uint32_t o = (uint32_t)(row*128 + kb); o ^= (o >> 3) & 0x70;
                ldsm4(a[mi][0], a[mi][1], a[mi][2], a[mi][3], sA + o);
            }
#pragma unroll
            for (int j = 0; j < 4; j++) {
                int row = wn*64 + j*16 + (lane & 15);
                uint32_t o = (uint32_t)(row*128 + kb); o ^= (o >> 3) & 0x70;
                ldsm4(b0[2*j], b0[2*j+1], b1[2*j], b1[2*j+1], sB + o);
            }
#pragma unroll
            for (int mi = 0; mi < 2; mi++)
#pragma unroll
                for (int ni = 0; ni < 8; ni++)
                    mma_f16(acc[mi][ni], a[mi], b0[ni], b1[ni]);
        }
        __syncthreads();
        if (c + 2 < NC) issue_load(c + 2, stg);
        CPCOMMIT;
    }
    CPWAIT(0);

    // epilogue
    const int g = lane >> 2, tq = lane & 3;
    const bool doRope = (EPI & 1) && (blockIdx.z < 2);
    const bool doQs   = (EPI & 32) && (blockIdx.z == 0);
#pragma unroll
    for (int mi = 0; mi < 2; mi++) {
#pragma unroll
        for (int ni = 0; ni < 8; ni++) {
            const int colb = n0 + wn*64 + ni*8 + 2*tq;
            float2 bv = make_float2(0.f, 0.f);
            if (EPI & 2) bv = *(const float2*)(bias + colb);
#pragma unroll
            for (int rh = 0; rh < 2; rh++) {
                int row = m0 + wm*32 + mi*16 + g + rh*8;
                float v0 = acc[mi][ni][rh*2], v1 = acc[mi][ni][rh*2+1];
                if (EPI & 2) { v0 += bv.x; v1 += bv.y; }
                if (EPI & 4) { v0 = fmaxf(v0, 0.f); v1 = fmaxf(v1, 0.f); }
                if (doRope) {
                    int t = row & (TT-1);
                    int pi = (colb & 63) >> 1;
                    float2 cs = rt[t*32 + pi];
                    float nv0 = v0*cs.x - v1*cs.y;
                    float nv1 = v0*cs.y + v1*cs.x;
                    v0 = nv0; v1 = nv1;
                }
                if (doQs) { v0 *= 0.125f; v1 *= 0.125f; }
                if (EPI & 8) {
                    float2 rv = *(const float2*)(res + (size_t)row*N + colb);
                    v0 += rv.x; v1 += rv.y;
                }
                if (EPI & 16) {
                    __half2 hv = __floats2half2_rn(v0, v1);
                    *(__half2*)(outH + (size_t)row*N + colb) = hv;
                } else {
                    *(float2*)(outF + (size_t)row*N + colb) = make_float2(v0, v1);
                }
            }
        }
    }
}

// ================= flash attention: fp16 in/out, 128-row Q tiles =================
__global__ void __launch_bounds__(256, 2) flash_kernel(
        const __half* __restrict__ qg, const __half* __restrict__ kg, const __half* __restrict__ vg,
        const uint32_t* __restrict__ mb, const int* __restrict__ mf,
        __half* __restrict__ attH) {
    extern __shared__ char smem_raw[];
    const uint32_t sbr = smem_u32(smem_raw);
    const uint32_t sb = (sbr + 1023) & ~1023u;
    char* base = smem_raw + (int)(sb - sbr);

    const uint32_t sQ = sb, sK = sb + 16384, sV = sb + 32768, sP = sb + 49152;

    int bh = blockIdx.y, b = bh >> 4, h = bh & 15;
    int t0 = blockIdx.x << 7;
    int tid = threadIdx.x, wid = tid >> 5, lane = tid & 31;
    int g = lane >> 2, tq = lane & 3;

    // effective block count from any-flags (data-driven)
    int nse = 0;
    const int* mfp = mf + b*32;
#pragma unroll
    for (int i2 = 0; i2 < 32; i2++) if (mfp[i2] & 1) nse = i2 + 1;

    const __half* kbase = kg + ((size_t)(b*TT)) * DD + h*64;
    const __half* vbase = vg + ((size_t)(b*TT)) * DD + h*64;

    const int lr = tid >> 3, lq = tid & 7;
    uint32_t lso = (uint32_t)((lr << 7) + (lq << 4));
    lso ^= (lso >> 3) & 0x70;

    auto issue_kv = [&](int s0, int stg) {
        const __half* ks = kbase + (size_t)s0 * DD;
        const __half* vs = vbase + (size_t)s0 * DD;
#pragma unroll
        for (int v = 0; v < 2; v++) {
            CPA(sK + stg*8192 + lso + v*4096, ks + (size_t)(lr + v*32)*DD + lq*8);
            CPA(sV + stg*8192 + lso + v*4096, vs + (size_t)(lr + v*32)*DD + lq*8);
        }
    };

    issue_kv(0, 0); CPCOMMIT;

    // load Q tile (scale already folded in)
    {
        const __half* src = qg + ((size_t)(b*TT) + t0) * DD + h*64;
#pragma unroll
        for (int v = 0; v < 4; v++) {
            int p = tid + (v << 8);
            int t = p >> 3, dq = p & 7;
            uint32_t o = (uint32_t)(t*128 + dq*16); o ^= (o >> 3) & 0x70;
            *(uint4*)(base + o) = *(const uint4*)(src + (size_t)t*DD + dq*8);
        }
    }

    float mrow[2] = {-1e30f, -1e30f};
    float lrow[2] = {0.f, 0.f};
    float o[8][4];
#pragma unroll
    for (int ni = 0; ni < 8; ni++)
#pragma unroll
        for (int v = 0; v < 4; v++) o[ni][v] = 0.f;

    for (int i = 0; i < nse; i++) {
        if (i + 1 < nse) { issue_kv((i+1)*64, (i+1) & 1); CPCOMMIT; CPWAIT(1); }
        else             { CPWAIT(0); }
        __syncthreads();
        const uint32_t kS = sK + (i & 1)*8192;
        const uint32_t vS = sV + (i & 1)*8192;
        const int s0 = i * 64;

        // S = Q K^T
        float sa[8][4];
#pragma unroll
        for (int ni = 0; ni < 8; ni++)
#pragma unroll
            for (int v = 0; v < 4; v++) sa[ni][v] = 0.f;
#pragma unroll
        for (int kk = 0; kk < 4; kk++) {
            const int kb = kk*32 + ((lane >> 4) << 4);
            uint32_t a[4], b0[8], b1[8];
            {
                int row = wid*16 + (lane & 15);
                uint32_t oo = (uint32_t)(row*128 + kb); oo ^= (oo >> 3) & 0x70;
                ldsm4(a[0], a[1], a[2], a[3], sQ + oo);
            }
#pragma unroll
            for (int j = 0; j < 4; j++) {
                int row = j*16 + (lane & 15);
                uint32_t oo = (uint32_t)(row*128 + kb); oo ^= (oo >> 3) & 0x70;
                ldsm4(b0[2*j], b0[2*j+1], b1[2*j], b1[2*j+1], kS + oo);
            }
#pragma unroll
            for (int ni = 0; ni < 8; ni++) mma_f16(sa[ni], a, b0[ni], b1[ni]);
        }

        // mask only when block not fully open
        if (!(mfp[i] & 2)) {
            int tr0 = t0 + wid*16 + g;
            const uint32_t* mrow0 = mb + ((size_t)(b*TT) + tr0)*(TT/32) + (s0 >> 5);
            const uint32_t* mrow1 = mrow0 + 8*(TT/32);
            uint32_t w00 = mrow0[0], w01 = mrow0[1];
            uint32_t w10 = mrow1[0], w11 = mrow1[1];
#pragma unroll
            for (int ni = 0; ni < 8; ni++) {
#pragma unroll
                for (int v = 0; v < 4; v++) {
                    int sc = ni*8 + 2*tq + (v & 1);
                    uint32_t wsel = (v < 2) ? ((sc < 32) ? w00 : w01)
                                            : ((sc < 32) ? w10 : w11);
                    bool ok = (wsel >> (sc & 31)) & 1u;
                    if (!ok) sa[ni][v] = -1e30f;
                }
            }
        }

        // online softmax
#pragma unroll
        for (int rh = 0; rh < 2; rh++) {
            float mx = -1e30f;
#pragma unroll
            for (int ni = 0; ni < 8; ni++)
                mx = fmaxf(mx, fmaxf(sa[ni][rh*2], sa[ni][rh*2+1]));
            mx = fmaxf(mx, __shfl_xor_sync(0xffffffffu, mx, 1));
            mx = fmaxf(mx, __shfl_xor_sync(0xffffffffu, mx, 2));
            float mn = fmaxf(mrow[rh], mx);
            float alpha = __expf(mrow[rh] - mn);
            mrow[rh] = mn;
            float rs = 0.f;
#pragma unroll
            for (int ni = 0; ni < 8; ni++) {
                float p0 = __expf(sa[ni][rh*2]   - mn);
                float p1 = __expf(sa[ni][rh*2+1] - mn);
                sa[ni][rh*2] = p0; sa[ni][rh*2+1] = p1;
                rs += p0 + p1;
            }
            rs += __shfl_xor_sync(0xffffffffu, rs, 1);
            rs += __shfl_xor_sync(0xffffffffu, rs, 2);
            lrow[rh] = lrow[rh]*alpha + rs;
#pragma unroll
            for (int ni = 0; ni < 8; ni++) { o[ni][rh*2] *= alpha; o[ni][rh*2+1] *= alpha; }
        }

        // P -> smem fp16
#pragma unroll
        for (int ni = 0; ni < 8; ni++) {
#pragma unroll
            for (int rh = 0; rh < 2; rh++) {
                int trow = wid*16 + g + rh*8;
                int scol = ni*8 + 2*tq;
                __half2 hp = __floats2half2_rn(sa[ni][rh*2], sa[ni][rh*2+1]);
                uint32_t oo = (uint32_t)(trow*128 + scol*2); oo ^= (oo >> 3) & 0x70;
                *(uint32_t*)(base + (sP - sb) + oo) = *(uint32_t*)&hp;
            }
        }
        __syncwarp();

        // O += P V
#pragma unroll
        for (int kk = 0; kk < 4; kk++) {
            uint32_t a[4], b0[8], b1[8];
            {
                int row = wid*16 + (lane & 15);
                uint32_t oo = (uint32_t)(row*128 + kk*32 + ((lane >> 4) << 4));
                oo ^= (oo >> 3) & 0x70;
                ldsm4(a[0], a[1], a[2], a[3], sP + oo);
            }
#pragma unroll
            for (int j = 0; j < 4; j++) {
                int rs_ = kk*16 + (lane & 15);
                uint32_t oo = (uint32_t)(rs_*128 + j*32 + ((lane >> 4) << 4));
                oo ^= (oo >> 3) & 0x70;
                ldsm4t(b0[2*j], b1[2*j], b0[2*j+1], b1[2*j+1], vS + oo);
            }
#pragma unroll
            for (int ni = 0; ni < 8; ni++) mma_f16(o[ni], a, b0[ni], b1[ni]);
        }
        __syncthreads();
    }

    // write att (fp16)
#pragma unroll
    for (int rh = 0; rh < 2; rh++) {
        float inv = 1.0f / lrow[rh];
        int t = t0 + wid*16 + g + rh*8;
        size_t rb = ((size_t)(b*TT) + t) * DD;
#pragma unroll
        for (int ni = 0; ni < 8; ni++) {
            int col = h*64 + ni*8 + 2*tq;
            __half2 hv = __floats2half2_rn(o[ni][rh*2] * inv, o[ni][rh*2+1] * inv);
            *(__half2*)(attH + rb + col) = hv;
        }
    }
}

// ================= launch =================
template<typename T>
static T* symaddr(const void* sym) {
    void* p = nullptr;
    cudaGetSymbolAddress(&p, sym);
    return (T*)p;
}

extern "C" void kernel_launch(void* const* d_in, const int* in_sizes, int n_in,
                              void* d_out, int out_size) {
    const float* x      = (const float*)d_in[0];
    const int*   mask   = (const int*)  d_in[1];
    const float* wq     = (const float*)d_in[2];
    const float* wk     = (const float*)d_in[3];
    const float* wv     = (const float*)d_in[4];
    const float* w_proj = (const float*)d_in[5];
    const float* b_proj = (const float*)d_in[6];
    const float* ln1_g  = (const float*)d_in[7];
    const float* ln1_b  = (const float*)d_in[8];
    const float* ln2_g  = (const float*)d_in[9];
    const float* ln2_b  = (const float*)d_in[10];
    const float* w1     = (const float*)d_in[11];
    const float* b1     = (const float*)d_in[12];
    const float* w2     = (const float*)d_in[13];
    const float* b2     = (const float*)d_in[14];
    float* out = (float*)d_out;

    __half* h16   = symaddr<__half>(g_h16);
    __half* qkv   = symaddr<__half>(g_qkv);
    __half* att   = symaddr<__half>(g_att);
    float*  x2_   = symaddr<float>(g_x2);
    __half* h216  = symaddr<__half>(g_h216);
    __half* ff    = symaddr<__half>(g_ff);
    __half* wqkvT = symaddr<__half>(g_wqkvT);
    __half* wpT   = symaddr<__half>(g_wpT);
    __half* w1T   = symaddr<__half>(g_w1T);
    __half* w2T   = symaddr<__half>(g_w2T);
    uint32_t* mb  = symaddr<uint32_t>(g_mb);
    int*    mf    = symaddr<int>(g_mf);
    float2* rt    = symaddr<float2>(g_rt);

    const int SMEM_MM = 2*32768 + 1024;   // 66560
    const int SMEM_FL = 4*16384 + 1024;   // 66560
    cudaFuncSetAttribute(mm16<49>, cudaFuncAttributeMaxDynamicSharedMemorySize, SMEM_MM);
    cudaFuncSetAttribute(mm16<10>, cudaFuncAttributeMaxDynamicSharedMemorySize, SMEM_MM);
    cudaFuncSetAttribute(mm16<22>, cudaFuncAttributeMaxDynamicSharedMemorySize, SMEM_MM);
    cudaFuncSetAttribute(flash_kernel, cudaFuncAttributeMaxDynamicSharedMemorySize, SMEM_FL);

    packmask_kernel<<<BB*TT*TT/256, 256>>>(mask, mb);
    maskflags_kernel<<<BB*32, 256>>>(mb, mf);
    ropetab_kernel<<<(TT*32 + 255)/256, 256>>>(rt);

    {
        dim3 blk(32, 8);
        wt16_kernel<<<dim3(DD/32, DD/32), blk>>>(wq, wqkvT, DD, DD);
        wt16_kernel<<<dim3(DD/32, DD/32), blk>>>(wk, wqkvT + (size_t)DD*DD, DD, DD);
        wt16_kernel<<<dim3(DD/32, DD/32), blk>>>(wv, wqkvT + 2*(size_t)DD*DD, DD, DD);
        wt16_kernel<<<dim3(DD/32, DD/32), blk>>>(w_proj, wpT, DD, DD);
        wt16_kernel<<<dim3(FF/32, DD/32), blk>>>(w1, w1T, DD, FF);
        wt16_kernel<<<dim3(DD/32, FF/32), blk>>>(w2, w2T, FF, DD);
    }

    // LN1 -> fp16
    ln16_kernel<<<NROWS, 256>>>(x, ln1_g, ln1_b, h16);

    // fused QKV GEMM: RoPE (z<2) + q-scale (z==0), fp16 out
    mm16<49><<<dim3(DD/128, NROWS/128, 3), 256, SMEM_MM>>>(
        h16, wqkvT, nullptr, nullptr, nullptr, qkv, DD, DD,
        (long)DD*DD, (long)NROWS*DD, rt);

    // flash attention
    flash_kernel<<<dim3(TT/128, NBH), 256, SMEM_FL>>>(
        qkv, qkv + (size_t)NROWS*DD, qkv + 2*(size_t)NROWS*DD, mb, mf, att);

    // proj + bias + residual -> x2 (fp32)
    mm16<10><<<dim3(DD/128, NROWS/128), 256, SMEM_MM>>>(
        att, wpT, b_proj, x, x2_, nullptr, DD, DD, 0L, 0L, rt);

    // LN2 -> fp16
    ln16_kernel<<<NROWS, 256>>>(x2_, ln2_g, ln2_b, h216);

    // MLP1: bias + relu -> fp16
    mm16<22><<<dim3(FF/128, NROWS/128), 256, SMEM_MM>>>(
        h216, w1T, b1, nullptr, nullptr, ff, FF, DD, 0L, 0L, rt);

    // MLP2: bias + residual -> out (fp32)
    mm16<10><<<dim3(DD/128, NROWS/128), 256, SMEM_MM>>>(
        ff, w2T, b2, x2_, out, nullptr, DD, FF, 0L, 0L, rt);
}